// round 13
// baseline (speedup 1.0000x reference)
#include <cuda_runtime.h>
#include <cuda_pipeline_primitives.h>
#include <math.h>

#define BB 4
#define CCH 64
#define G_PER 4            // snake groups/block (both levels)
#define GF    4            // fused final kernel groups/block
#define NHALO 612          // 34 x 18 halo points
#define NRAW  836          // 38 x 22 raw t tile
#define NXT   2244         // 34 x 66 x-tile points
#define SXPITCH 68

__device__ __align__(16) float g_t0  [(size_t)4*64*128*128*4];
__device__ __align__(16) float g_t1  [(size_t)4*64*64*64*4];
__device__ __align__(16) float g_tpw1[(size_t)4*64*64*64*4];
__device__ __align__(8) float g_off0[(size_t)4*2*128*128];
__device__ __align__(8) float g_off1[(size_t)4*2*64*64];
__device__ float g_offacc[(size_t)8*4*2*128*128];

// Two-level Haar analysis; 4-wide x 8-tall patch, float4 loads, coalesced t0+t1 stores.
__global__ void k_wt2(const float* __restrict__ src, float4* __restrict__ t0,
                      float4* __restrict__ t1) {
    int idx = blockIdx.x * blockDim.x + threadIdx.x;
    int q = idx & 63;          // 4-col group
    int t = idx >> 6;
    int p = t & 31;            // 8-row group
    t >>= 5;
    int c = t & 63; int b = t >> 6;
    const float4* s = (const float4*)(src + ((size_t)(b*64+c)*256 + 8*p)*256) + q;
    float4* t0b = t0 + (size_t)(b*64+c)*128*128;
    float LLs[4][2];
    #pragma unroll
    for (int rr=0; rr<4; rr++){
        float4 a = s[(size_t)(2*rr)*64];
        float4 d = s[(size_t)(2*rr+1)*64];
        float4 o0 = make_float4(0.5f*(a.x+a.y+d.x+d.y), 0.5f*(a.x+a.y-d.x-d.y),
                                0.5f*(a.x-a.y+d.x-d.y), 0.5f*(a.x-a.y-d.x+d.y));
        float4 o1 = make_float4(0.5f*(a.z+a.w+d.z+d.w), 0.5f*(a.z+a.w-d.z-d.w),
                                0.5f*(a.z-a.w+d.z-d.w), 0.5f*(a.z-a.w-d.z+d.w));
        t0b[(size_t)(4*p+rr)*128 + 2*q]     = o0;
        t0b[(size_t)(4*p+rr)*128 + 2*q + 1] = o1;
        LLs[rr][0]=o0.x; LLs[rr][1]=o1.x;
    }
    float4* t1b = t1 + (size_t)(b*64+c)*64*64;
    #pragma unroll
    for (int jr=0;jr<2;jr++){
        float x00=LLs[2*jr][0], x01=LLs[2*jr][1];
        float x10=LLs[2*jr+1][0], x11=LLs[2*jr+1][1];
        t1b[(size_t)(2*p+jr)*64 + q] = make_float4(
            0.5f*(x00+x01+x10+x11), 0.5f*(x00+x01-x10-x11),
            0.5f*(x00-x01+x10-x11), 0.5f*(x00-x01-x10+x11));
    }
}

// packed bilinear state: (i0, dx|dyo<<8, wx, wy); i0<0 => outside image (td=0)
__device__ __forceinline__ float4 make_pack(int i, const float2* __restrict__ ofp,
                                            int gx0, int gy0, int tx0, int ty0,
                                            int Hh, int Ww) {
    int xx=i%34, yy=i/34;
    int gx=gx0+xx, gy=gy0+yy;
    float4 pk = make_float4(__int_as_float(-1), 0.f, 0.f, 0.f);
    if (gx>=0&&gx<Ww&&gy>=0&&gy<Hh){
        float2 c = ofp[(size_t)gy*Ww+gx];
        float x0=floorf(c.x), y0=floorf(c.y);
        int x0i=(int)x0, y0i=(int)y0;
        int dx = min(x0i+1,Ww-1)-x0i;
        int dyo = (min(y0i+1,Hh-1)-y0i)*38;
        int i0 = (y0i-ty0)*38 + (x0i-tx0);
        pk = make_float4(__int_as_float(i0), __int_as_float(dx | (dyo<<8)),
                         c.x-x0, c.y-y0);
    }
    return pk;
}

__device__ __forceinline__ float4 gather_one(float4 pk, const float4* sraw) {
    int i0 = __float_as_int(pk.x);
    float4 r = make_float4(0.f,0.f,0.f,0.f);
    if (i0 >= 0) {
        int code = __float_as_int(pk.y);
        int dx = code & 0xff, dyo = code >> 8;
        float wx = pk.z, wy = pk.w;
        float u = 1.f-wx, v = 1.f-wy;
        float w00=v*u, w01=v*wx, w10=wy*u, w11=wy*wx;
        float4 a=sraw[i0], b=sraw[i0+dx], c=sraw[i0+dyo], d=sraw[i0+dyo+dx];
        r.x=a.x*w00+b.x*w01+c.x*w10+d.x*w11;
        r.y=a.y*w00+b.y*w01+c.y*w10+d.y*w11;
        r.z=a.z*w00+b.z*w01+c.z*w10+d.z*w11;
        r.w=a.w*w00+b.w*w01+c.w*w10+d.w*w11;
    }
    return r;
}

// ---------------- off2 body (dense 3x3 conv 256->2, channel split) ----------------
__device__ __forceinline__ void off2_body(char* sm, const float4* __restrict__ t4,
                                          const float* __restrict__ ow,
                                          float* __restrict__ acc, int Hh, int Ww,
                                          int bxx, int byy, int bzz) {
    float* wsm = (float*)sm;                               // 576 floats
    float (*tile)[34][34] = (float(*)[34][34])(sm + 2304); // 8x34x34
    int tx=threadIdx.x, ty=threadIdx.y, tid=ty*32+tx;
    int split = bzz & 7, b = bzz >> 3;
    int cb = split*32, gb = split*8;
    for (int i=tid;i<576;i+=256){int o=i/288,rem=i%288;wsm[i]=ow[(o*256+cb+rem/9)*9+rem%9];}
    size_t plane = (size_t)Hh*Ww;
    const float4* tb = t4 + (size_t)b*64*plane;
    int gx0 = bxx*32-1, gy0 = byy*32-1;
    float a0[4]={0,0,0,0}, a1[4]={0,0,0,0};
    for (int gg=0; gg<8; gg+=2) {
        __syncthreads();
        for (int i=tid;i<2*1156;i+=256){
            int g2=i/1156,pos=i%1156,yy=pos/34,xx=pos%34;
            int gy=gy0+yy, gx=gx0+xx;
            float4 v = make_float4(0.f,0.f,0.f,0.f);
            if (gy>=0&&gy<Hh&&gx>=0&&gx<Ww) v = tb[(size_t)(gb+gg+g2)*plane+(size_t)gy*Ww+gx];
            tile[g2*4+0][yy][xx]=v.x; tile[g2*4+1][yy][xx]=v.y;
            tile[g2*4+2][yy][xx]=v.z; tile[g2*4+3][yy][xx]=v.w;
        }
        __syncthreads();
        #pragma unroll
        for (int c8=0;c8<8;c8++){
            int lc = gg*4 + c8;
            float w0[9], w1[9];
            #pragma unroll
            for (int k=0;k<9;k++){w0[k]=wsm[lc*9+k];w1[k]=wsm[288+lc*9+k];}
            float vals[6][3];
            #pragma unroll
            for (int rr=0;rr<6;rr++)
                #pragma unroll
                for (int kx=0;kx<3;kx++) vals[rr][kx]=tile[c8][4*ty+rr][tx+kx];
            #pragma unroll
            for (int r=0;r<4;r++)
                #pragma unroll
                for (int ky=0;ky<3;ky++)
                    #pragma unroll
                    for (int kx=0;kx<3;kx++){
                        float v=vals[r+ky][kx];
                        a0[r]+=v*w0[ky*3+kx]; a1[r]+=v*w1[ky*3+kx];
                    }
        }
    }
    float* ob = acc + (((size_t)split*4 + b)*2)*plane;
    int px = bxx*32+tx;
    #pragma unroll
    for (int r=0;r<4;r++){
        int py = byy*32 + ty*4 + r;
        ob[(size_t)py*Ww+px]=a0[r];
        ob[plane+(size_t)py*Ww+px]=a1[r];
    }
}

__global__ void k_off2(const float4* __restrict__ t4, const float* __restrict__ ow,
                       float* __restrict__ acc, int Hh, int Ww) {
    __shared__ __align__(16) char sm[39296];
    off2_body(sm, t4, ow, acc, Hh, Ww, blockIdx.x, blockIdx.y, blockIdx.z);
}

__device__ __forceinline__ float reflect_clip(float v, float size) {
    float two = 2.f*size;
    float r = fmodf(v+0.5f, two);
    if (r < 0.f) r += two;
    if (r > size) r = two - r;
    r -= 0.5f;
    return fminf(fmaxf(r, 0.f), size-1.f);
}

__global__ void k_offfin(const float* __restrict__ acc, const float* __restrict__ ob,
                         float2* __restrict__ offmap, int Hh, int Ww) {
    int idx = blockIdx.x*blockDim.x + threadIdx.x;
    int n = BB*Hh*Ww;
    if (idx >= n) return;
    int px = idx % Ww; int t = idx / Ww;
    int py = t % Hh; int b = t / Hh;
    size_t plane = (size_t)Hh*Ww, pix = (size_t)py*Ww+px;
    float s0=0.f, s1=0.f;
    #pragma unroll
    for (int s=0;s<8;s++){
        const float* base = acc + (((size_t)s*4+b)*2)*plane + pix;
        s0 += base[0]; s1 += base[plane];
    }
    float offx = tanhf(s0 + ob[0]);
    float offy = tanhf(s1 + ob[1]);
    float w = (float)Ww, h = (float)Hh;
    float ix = ((float)px + offx) * (w/(w-1.f)) - 0.5f;
    float iy = ((float)py + offy) * (h/(h-1.f)) - 0.5f;
    offmap[(size_t)b*plane + pix] = make_float2(reflect_clip(ix, w), reflect_clip(iy, h));
}

// ---------------- sdp body (snake: gather->dw->relu->pw->wscale), packed state -----
__device__ __forceinline__ void sdp_body(char* sm, const float4* __restrict__ t4,
                                         const float2* __restrict__ offmap,
                                         const float* __restrict__ dww,
                                         const float* __restrict__ pww,
                                         const float* __restrict__ wsc,
                                         float4* __restrict__ outp, int Hh, int Ww,
                                         int bxx, int byy, int bzz) {
    float4* spk  = (float4*)sm;                        // 612*16 = 9792
    float4* sraw = (float4*)(sm + 9792);               // 836*16 = 13376 -> 23168
    float4* td   = (float4*)(sm + 23168);              // 9792 -> 32960
    float4* sdw4 = (float4*)(sm + 32960);              // 576
    float4* spw  = (float4*)(sm + 33536);              // 256
    float4* sws  = (float4*)(sm + 33792);              // 64 -> 33856 total
    int tx=threadIdx.x, ty=threadIdx.y, tid=ty*32+tx;
    int b = bzz >> 4, g0 = (bzz & 15)*G_PER;
    if (tid < G_PER*9) {
        int gi = tid/9, k = tid%9, c4 = (g0+gi)*4;
        sdw4[tid] = make_float4(dww[(c4+0)*9+k], dww[(c4+1)*9+k],
                                dww[(c4+2)*9+k], dww[(c4+3)*9+k]);
    }
    if (tid < G_PER*4) spw[tid] = *(const float4*)&pww[(g0*4+tid)*4];
    if (tid < G_PER)   sws[tid] = *(const float4*)&wsc[(g0+tid)*4];
    size_t plane = (size_t)Hh*Ww;
    const float2* ofp = offmap + (size_t)b*plane;
    int gx0 = bxx*32-1, gy0 = byy*16-1;
    int tx0 = gx0-2, ty0 = gy0-2;
    const float4* tb = t4 + (size_t)b*64*plane;
    {
        const float4* tg = tb + (size_t)g0*plane;
        for (int i=tid;i<NRAW;i+=256){
            int r=i/38, c=i%38;
            int gy=min(max(ty0+r,0),Hh-1), gx=min(max(tx0+c,0),Ww-1);
            __pipeline_memcpy_async(&sraw[i], &tg[(size_t)gy*Ww+gx], 16);
        }
        __pipeline_commit();
    }
    for (int i=tid;i<NHALO;i+=256)
        spk[i] = make_pack(i, ofp, gx0, gy0, tx0, ty0, Hh, Ww);
    int px = bxx*32+tx, py0 = byy*16 + 2*ty;
    __pipeline_wait_prior(0);
    __syncthreads();
    for (int gi=0; gi<G_PER; gi++) {
        int g = g0 + gi;
        for (int i=tid;i<NHALO;i+=256)
            td[i] = gather_one(spk[i], sraw);
        __syncthreads();
        if (gi+1 < G_PER){
            const float4* tg = tb + (size_t)(g+1)*plane;
            for (int i=tid;i<NRAW;i+=256){
                int r=i/38, c=i%38;
                int gy=min(max(ty0+r,0),Hh-1), gx=min(max(tx0+c,0),Ww-1);
                __pipeline_memcpy_async(&sraw[i], &tg[(size_t)gy*Ww+gx], 16);
            }
            __pipeline_commit();
        }
        float4 acc0=make_float4(0,0,0,0), acc1=make_float4(0,0,0,0);
        #pragma unroll
        for (int ky=0; ky<4; ky++){
            const float4* trow = &td[(2*ty+ky)*34 + tx];
            float4 v0=trow[0], v1=trow[1], v2=trow[2];
            if (ky < 3) {
                const float4* wr = &sdw4[gi*9 + ky*3];
                float4 w0=wr[0], w1=wr[1], w2=wr[2];
                acc0.x += v0.x*w0.x + v1.x*w1.x + v2.x*w2.x;
                acc0.y += v0.y*w0.y + v1.y*w1.y + v2.y*w2.y;
                acc0.z += v0.z*w0.z + v1.z*w1.z + v2.z*w2.z;
                acc0.w += v0.w*w0.w + v1.w*w1.w + v2.w*w2.w;
            }
            if (ky >= 1) {
                const float4* wr = &sdw4[gi*9 + (ky-1)*3];
                float4 w0=wr[0], w1=wr[1], w2=wr[2];
                acc1.x += v0.x*w0.x + v1.x*w1.x + v2.x*w2.x;
                acc1.y += v0.y*w0.y + v1.y*w1.y + v2.y*w2.y;
                acc1.z += v0.z*w0.z + v1.z*w1.z + v2.z*w2.z;
                acc1.w += v0.w*w0.w + v1.w*w1.w + v2.w*w2.w;
            }
        }
        float4 p0=spw[gi*4],p1=spw[gi*4+1],p2=spw[gi*4+2],p3=spw[gi*4+3],wsv=sws[gi];
        float4* og = outp + ((size_t)b*64+g)*plane;
        #pragma unroll
        for (int r=0;r<2;r++){
            float4 ac = r ? acc1 : acc0;
            float r0=fmaxf(ac.x,0.f), r1=fmaxf(ac.y,0.f);
            float r2=fmaxf(ac.z,0.f), r3=fmaxf(ac.w,0.f);
            float4 o;
            o.x=(r0*p0.x+r1*p0.y+r2*p0.z+r3*p0.w)*wsv.x;
            o.y=(r0*p1.x+r1*p1.y+r2*p1.z+r3*p1.w)*wsv.y;
            o.z=(r0*p2.x+r1*p2.y+r2*p2.z+r3*p2.w)*wsv.z;
            o.w=(r0*p3.x+r1*p3.y+r2*p3.z+r3*p3.w)*wsv.w;
            og[(size_t)(py0+r)*Ww + px] = o;
        }
        __pipeline_wait_prior(0);
        __syncthreads();
    }
}

// ---------------- merged kernel: even blocks = snake-L1, odd blocks = off2-L0 -------
__global__ void __launch_bounds__(256, 4)
k_mix(const float4* __restrict__ t1, const float2* __restrict__ off1,
      const float* __restrict__ dww1, const float* __restrict__ pww1,
      const float* __restrict__ wsc1, float4* __restrict__ tpw1,
      const float4* __restrict__ t0, const float* __restrict__ ow0,
      float* __restrict__ acc0) {
    __shared__ __align__(16) char sm[39296];
    int role = blockIdx.x & 1, idx = blockIdx.x >> 1;
    if (role == 0) {
        int bxx = idx & 1, byy = (idx >> 1) & 3, bzz = idx >> 3;
        sdp_body(sm, t1, off1, dww1, pww1, wsc1, tpw1, 64, 64, bxx, byy, bzz);
    } else {
        int bxx = idx & 3, byy = (idx >> 2) & 3, bzz = idx >> 4;
        off2_body(sm, t0, ow0, acc0, 128, 128, bxx, byy, bzz);
    }
}

// ---------------- level-0 snake + final reconstruction fused (GF=4) ----------------
__global__ void __launch_bounds__(256, 4)
k_sdpfin(const float4* __restrict__ t4, const float2* __restrict__ offmap,
         const float* __restrict__ dww, const float* __restrict__ pww,
         const float* __restrict__ wsc, const float4* __restrict__ tpw1,
         const float* __restrict__ xin, const float* __restrict__ bw,
         const float* __restrict__ bb_, const float* __restrict__ bscale,
         const float* __restrict__ gammap, float* __restrict__ outp) {
    const int Hh=128, Ww=128;
    __shared__ __align__(16) float4 sraw[NRAW];
    __shared__ __align__(16) float4 td  [NHALO];
    __shared__ __align__(16) float sxf[34*SXPITCH];
    __shared__ float4 sdw4[GF*9];
    __shared__ float4 spw[GF*4];
    __shared__ float4 sws[GF];
    __shared__ float  sbw[GF*9];
    __shared__ float  sbb[GF], ssc[GF];
    int tx=threadIdx.x, ty=threadIdx.y, tid=ty*32+tx;
    int bx=blockIdx.x, by=blockIdx.y;
    int b = blockIdx.z >> 4, g0 = (blockIdx.z & 15)*GF;
    if (tid < GF*9) {
        int gi = tid/9, k = tid%9, c4 = (g0+gi)*4;
        sdw4[tid] = make_float4(dww[(c4+0)*9+k], dww[(c4+1)*9+k],
                                dww[(c4+2)*9+k], dww[(c4+3)*9+k]);
        sbw[tid] = bw[g0*9 + tid];
    }
    if (tid < GF*4) spw[tid] = *(const float4*)&pww[(g0*4+tid)*4];
    if (tid < GF) {
        sws[tid] = *(const float4*)&wsc[(g0+tid)*4];
        sbb[tid] = bb_[g0+tid];
        ssc[tid] = bscale[g0+tid];
    }
    float gm = __ldg(gammap);
    size_t plane = (size_t)Hh*Ww;
    const float2* ofp = offmap + (size_t)b*plane;
    int gx0 = bx*32-1, gy0 = by*16-1;
    int tx0 = gx0-2, ty0 = gy0-2;
    const float4* tb = t4 + (size_t)b*64*plane;
    {
        const float4* tg = tb + (size_t)g0*plane;
        for (int i=tid;i<NRAW;i+=256){
            int r=i/38, c=i%38;
            int gy=min(max(ty0+r,0),Hh-1), gx=min(max(tx0+c,0),Ww-1);
            __pipeline_memcpy_async(&sraw[i], &tg[(size_t)gy*Ww+gx], 16);
        }
        __pipeline_commit();
        const float* xg = xin + ((size_t)b*64+g0)*65536;
        for (int i=tid;i<NXT;i+=256){
            int sr=i/66, sc=i%66;
            int gy=32*by-1+sr, gxc=64*bx-1+sc;
            float* dst = &sxf[sr*SXPITCH+sc];
            if (gy>=0&&gy<256&&gxc>=0&&gxc<256)
                __pipeline_memcpy_async(dst, &xg[(size_t)gy*256+gxc], 4);
            else *dst = 0.f;
        }
        __pipeline_commit();
    }
    // packed bilinear state kept in registers (3 slots: tid, tid+256, tid+512)
    float4 pk0 = make_pack(tid,       ofp, gx0, gy0, tx0, ty0, Hh, Ww);
    float4 pk1 = make_pack(tid + 256, ofp, gx0, gy0, tx0, ty0, Hh, Ww);
    float4 pk2 = make_float4(__int_as_float(-1), 0.f, 0.f, 0.f);
    if (tid < 100) pk2 = make_pack(tid + 512, ofp, gx0, gy0, tx0, ty0, Hh, Ww);
    int pxc = bx*32+tx, py0 = by*16 + 2*ty;
    __pipeline_wait_prior(0);
    __syncthreads();
    for (int gi=0; gi<GF; gi++) {
        int g = g0 + gi;
        td[tid]       = gather_one(pk0, sraw);
        td[tid + 256] = gather_one(pk1, sraw);
        if (tid < 100) td[tid + 512] = gather_one(pk2, sraw);
        __syncthreads();
        if (gi+1 < GF){
            const float4* tg = tb + (size_t)(g+1)*plane;
            for (int i=tid;i<NRAW;i+=256){
                int r=i/38, c=i%38;
                int gy=min(max(ty0+r,0),Hh-1), gx=min(max(tx0+c,0),Ww-1);
                __pipeline_memcpy_async(&sraw[i], &tg[(size_t)gy*Ww+gx], 16);
            }
            __pipeline_commit();
        }
        float4 acc0=make_float4(0,0,0,0), acc1=make_float4(0,0,0,0);
        #pragma unroll
        for (int ky=0; ky<4; ky++){
            const float4* trow = &td[(2*ty+ky)*34 + tx];
            float4 v0=trow[0], v1=trow[1], v2=trow[2];
            if (ky < 3) {
                const float4* wr = &sdw4[gi*9 + ky*3];
                float4 w0=wr[0], w1=wr[1], w2=wr[2];
                acc0.x += v0.x*w0.x + v1.x*w1.x + v2.x*w2.x;
                acc0.y += v0.y*w0.y + v1.y*w1.y + v2.y*w2.y;
                acc0.z += v0.z*w0.z + v1.z*w1.z + v2.z*w2.z;
                acc0.w += v0.w*w0.w + v1.w*w1.w + v2.w*w2.w;
            }
            if (ky >= 1) {
                const float4* wr = &sdw4[gi*9 + (ky-1)*3];
                float4 w0=wr[0], w1=wr[1], w2=wr[2];
                acc1.x += v0.x*w0.x + v1.x*w1.x + v2.x*w2.x;
                acc1.y += v0.y*w0.y + v1.y*w1.y + v2.y*w2.y;
                acc1.z += v0.z*w0.z + v1.z*w1.z + v2.z*w2.z;
                acc1.w += v0.w*w0.w + v1.w*w1.w + v2.w*w2.w;
            }
        }
        float4 p0=spw[gi*4],p1=spw[gi*4+1],p2=spw[gi*4+2],p3=spw[gi*4+3],wsv=sws[gi];
        float4 o0, o1;
        {
            float r0=fmaxf(acc0.x,0.f), r1=fmaxf(acc0.y,0.f);
            float r2=fmaxf(acc0.z,0.f), r3=fmaxf(acc0.w,0.f);
            o0.x=(r0*p0.x+r1*p0.y+r2*p0.z+r3*p0.w)*wsv.x;
            o0.y=(r0*p1.x+r1*p1.y+r2*p1.z+r3*p1.w)*wsv.y;
            o0.z=(r0*p2.x+r1*p2.y+r2*p2.z+r3*p2.w)*wsv.z;
            o0.w=(r0*p3.x+r1*p3.y+r2*p3.z+r3*p3.w)*wsv.w;
            r0=fmaxf(acc1.x,0.f); r1=fmaxf(acc1.y,0.f);
            r2=fmaxf(acc1.z,0.f); r3=fmaxf(acc1.w,0.f);
            o1.x=(r0*p0.x+r1*p0.y+r2*p0.z+r3*p0.w)*wsv.x;
            o1.y=(r0*p1.x+r1*p1.y+r2*p1.z+r3*p1.w)*wsv.y;
            o1.z=(r0*p2.x+r1*p2.y+r2*p2.z+r3*p2.w)*wsv.z;
            o1.w=(r0*p3.x+r1*p3.y+r2*p3.z+r3*p3.w)*wsv.w;
        }
        if (gi+1 < GF) __pipeline_wait_prior(1);
        else           __pipeline_wait_prior(0);
        float4 n = tpw1[((size_t)(b*64+g)*64 + (py0>>1))*64 + (pxc>>1)];
        float sB = (pxc & 1) ? -1.f : 1.f;
        float nz = sB*n.z, nw = sB*n.w;
        float LL0 = o0.x + 0.5f*(n.x + n.y + nz + nw);
        float LL1 = o1.x + 0.5f*(n.x - n.y + nz - nw);
        float rec[4][2];
        rec[0][0]=0.5f*(LL0+o0.y+o0.z+o0.w); rec[0][1]=0.5f*(LL0+o0.y-o0.z-o0.w);
        rec[1][0]=0.5f*(LL0-o0.y+o0.z-o0.w); rec[1][1]=0.5f*(LL0-o0.y-o0.z+o0.w);
        rec[2][0]=0.5f*(LL1+o1.y+o1.z+o1.w); rec[2][1]=0.5f*(LL1+o1.y-o1.z-o1.w);
        rec[3][0]=0.5f*(LL1-o1.y+o1.z-o1.w); rec[3][1]=0.5f*(LL1-o1.y-o1.z+o1.w);
        float bw0=sbw[gi*9],bw1=sbw[gi*9+1],bw2=sbw[gi*9+2];
        float bw3=sbw[gi*9+3],bw4=sbw[gi*9+4],bw5=sbw[gi*9+5];
        float bw6=sbw[gi*9+6],bw7=sbw[gi*9+7],bw8=sbw[gi*9+8];
        float bias=sbb[gi], sc=ssc[gi];
        float* og = outp + ((size_t)b*64+g)*65536;
        int scol = 2*tx, srow0 = 4*ty;
        float r0c[4], r1c[4], r2c[4];
        #pragma unroll
        for (int k=0;k<4;k++){ r0c[k]=sxf[srow0*SXPITCH+scol+k];
                               r1c[k]=sxf[(srow0+1)*SXPITCH+scol+k]; }
        #pragma unroll
        for (int oi=0; oi<4; oi++){
            #pragma unroll
            for (int k=0;k<4;k++) r2c[k]=sxf[(srow0+oi+2)*SXPITCH+scol+k];
            float c0 = r0c[0]*bw0+r0c[1]*bw1+r0c[2]*bw2
                     + r1c[0]*bw3+r1c[1]*bw4+r1c[2]*bw5
                     + r2c[0]*bw6+r2c[1]*bw7+r2c[2]*bw8;
            float c1 = r0c[1]*bw0+r0c[2]*bw1+r0c[3]*bw2
                     + r1c[1]*bw3+r1c[2]*bw4+r1c[3]*bw5
                     + r2c[1]*bw6+r2c[2]*bw7+r2c[3]*bw8;
            int orow = 32*by + 4*ty + oi;
            float ov0 = (c0+bias)*sc + gm*rec[oi][0];
            float ov1 = (c1+bias)*sc + gm*rec[oi][1];
            *(float2*)&og[(size_t)orow*256 + 64*bx + 2*tx] = make_float2(ov0, ov1);
            #pragma unroll
            for (int k=0;k<4;k++){ r0c[k]=r1c[k]; r1c[k]=r2c[k]; }
        }
        __syncthreads();
        if (gi+1 < GF){
            const float* xg = xin + ((size_t)b*64+g+1)*65536;
            for (int i=tid;i<NXT;i+=256){
                int sr=i/66, sc=i%66;
                int gy=32*by-1+sr, gxc=64*bx-1+sc;
                float* dst = &sxf[sr*SXPITCH+sc];
                if (gy>=0&&gy<256&&gxc>=0&&gxc<256)
                    __pipeline_memcpy_async(dst, &xg[(size_t)gy*256+gxc], 4);
                else *dst = 0.f;
            }
            __pipeline_commit();
            __pipeline_wait_prior(1);
        }
        __syncthreads();
    }
}

extern "C" void kernel_launch(void* const* d_in, const int* in_sizes, int n_in,
                              void* d_out, int out_size) {
    const float* x       = (const float*)d_in[0];
    const float* base_w  = (const float*)d_in[1];
    const float* base_b  = (const float*)d_in[2];
    const float* base_sc = (const float*)d_in[3];
    const float* off_w   = (const float*)d_in[4];
    const float* off_b   = (const float*)d_in[5];
    const float* dw_w    = (const float*)d_in[6];
    const float* pw_w    = (const float*)d_in[7];
    const float* wscale  = (const float*)d_in[8];
    const float* gamma   = (const float*)d_in[9];
    float* out = (float*)d_out;

    float4 *t0, *t1, *tpw1;
    float *off0, *off1, *offacc;
    cudaGetSymbolAddress((void**)&t0,   g_t0);
    cudaGetSymbolAddress((void**)&t1,   g_t1);
    cudaGetSymbolAddress((void**)&tpw1, g_tpw1);
    cudaGetSymbolAddress((void**)&off0, g_off0);
    cudaGetSymbolAddress((void**)&off1, g_off1);
    cudaGetSymbolAddress((void**)&offacc, g_offacc);

    // both wavelet levels in one pass
    k_wt2<<<2048, 256>>>(x, t0, t1);
    // level-1 offsets
    k_off2<<<dim3(2,2,32), dim3(32,8)>>>(t1, off_w + 2*256*9, offacc, 64, 64);
    k_offfin<<<64, 256>>>(offacc, off_b + 2, (float2*)off1, 64, 64);
    // merged: level-1 snake (even blocks) + level-0 offset conv (odd blocks)
    k_mix<<<1024, dim3(32,8)>>>(t1, (const float2*)off1, dw_w + 256*9, pw_w + 256*4,
                                wscale + 256, tpw1, t0, off_w, offacc);
    // level-0 offset finalize
    k_offfin<<<256, 256>>>(offacc, off_b, (float2*)off0, 128, 128);
    // level-0 snake + full reconstruction + base, fused
    k_sdpfin<<<dim3(4,8,64), dim3(32,8)>>>(t0, (const float2*)off0, dw_w, pw_w, wscale,
                                           tpw1, x, base_w, base_b, base_sc, gamma, out);
}

// round 14
// speedup vs baseline: 1.0487x; 1.0487x over previous
#include <cuda_runtime.h>
#include <cuda_pipeline_primitives.h>
#include <math.h>

#define BB 4
#define CCH 64
#define G_PER 4            // snake groups/block (both levels)
#define GF    4            // fused final kernel groups/block
#define NHALO 612          // 34 x 18 halo points
#define NRAW  836          // 38 x 22 raw t tile
#define NXT   2244         // 34 x 66 x-tile points
#define SXPITCH 68

__device__ __align__(16) float g_t0  [(size_t)4*64*128*128*4];
__device__ __align__(16) float g_t1  [(size_t)4*64*64*64*4];
__device__ __align__(16) float g_tpw1[(size_t)4*64*64*64*4];
__device__ __align__(8) float g_off0[(size_t)4*2*128*128];
__device__ __align__(8) float g_off1[(size_t)4*2*64*64];
__device__ float g_offacc[(size_t)8*4*2*128*128];

// Two-level Haar analysis fused, coalesced stores (R12-proven shfl version).
__global__ void k_wt2(const float* __restrict__ src, float4* __restrict__ t0,
                      float4* __restrict__ t1) {
    int idx = blockIdx.x * blockDim.x + threadIdx.x;
    int q = idx & 127;
    int t = idx >> 7;
    int p = t & 31;
    t >>= 5;
    int c = t & 63; int b = t >> 6;
    const float* s = src + ((size_t)(b*64+c)*256 + 8*p)*256 + 2*q;
    float2 rowv[8];
    #pragma unroll
    for (int r=0;r<8;r++) rowv[r] = *(const float2*)(s + (size_t)r*256);
    float4* t0b = t0 + (size_t)(b*64+c)*128*128;
    float LL[4];
    #pragma unroll
    for (int rr=0; rr<4; rr++){
        float x00=rowv[2*rr].x, x01=rowv[2*rr].y;
        float x10=rowv[2*rr+1].x, x11=rowv[2*rr+1].y;
        float LLv=0.5f*(x00+x01+x10+x11), A=0.5f*(x00+x01-x10-x11);
        float Bv=0.5f*(x00-x01+x10-x11), Cv=0.5f*(x00-x01-x10+x11);
        t0b[(size_t)(4*p+rr)*128 + q] = make_float4(LLv,A,Bv,Cv);
        LL[rr]=LLv;
    }
    float LLp[4];
    #pragma unroll
    for (int rr=0;rr<4;rr++) LLp[rr] = __shfl_down_sync(0xffffffffu, LL[rr], 1);
    if (!(q & 1)) {
        float4* t1b = t1 + (size_t)(b*64+c)*64*64;
        #pragma unroll
        for (int jr=0;jr<2;jr++){
            float x00=LL[2*jr], x01=LLp[2*jr], x10=LL[2*jr+1], x11=LLp[2*jr+1];
            t1b[(size_t)(2*p+jr)*64 + (q>>1)] = make_float4(
                0.5f*(x00+x01+x10+x11), 0.5f*(x00+x01-x10-x11),
                0.5f*(x00-x01+x10-x11), 0.5f*(x00-x01-x10+x11));
        }
    }
}

// packed bilinear state: (i0, dx|dyo<<8, wx, wy); i0<0 => outside image (td=0)
__device__ __forceinline__ float4 make_pack(int i, const float2* __restrict__ ofp,
                                            int gx0, int gy0, int tx0, int ty0,
                                            int Hh, int Ww) {
    int xx=i%34, yy=i/34;
    int gx=gx0+xx, gy=gy0+yy;
    float4 pk = make_float4(__int_as_float(-1), 0.f, 0.f, 0.f);
    if (gx>=0&&gx<Ww&&gy>=0&&gy<Hh){
        float2 c = ofp[(size_t)gy*Ww+gx];
        float x0=floorf(c.x), y0=floorf(c.y);
        int x0i=(int)x0, y0i=(int)y0;
        int dx = min(x0i+1,Ww-1)-x0i;
        int dyo = (min(y0i+1,Hh-1)-y0i)*38;
        int i0 = (y0i-ty0)*38 + (x0i-tx0);
        pk = make_float4(__int_as_float(i0), __int_as_float(dx | (dyo<<8)),
                         c.x-x0, c.y-y0);
    }
    return pk;
}

__device__ __forceinline__ float4 gather_one(float4 pk, const float4* sraw) {
    int i0 = __float_as_int(pk.x);
    float4 r = make_float4(0.f,0.f,0.f,0.f);
    if (i0 >= 0) {
        int code = __float_as_int(pk.y);
        int dx = code & 0xff, dyo = code >> 8;
        float wx = pk.z, wy = pk.w;
        float u = 1.f-wx, v = 1.f-wy;
        float w00=v*u, w01=v*wx, w10=wy*u, w11=wy*wx;
        float4 a=sraw[i0], b=sraw[i0+dx], c=sraw[i0+dyo], d=sraw[i0+dyo+dx];
        r.x=a.x*w00+b.x*w01+c.x*w10+d.x*w11;
        r.y=a.y*w00+b.y*w01+c.y*w10+d.y*w11;
        r.z=a.z*w00+b.z*w01+c.z*w10+d.z*w11;
        r.w=a.w*w00+b.w*w01+c.w*w10+d.w*w11;
    }
    return r;
}

// ---------------- off2 body (dense 3x3 conv 256->2, channel split) ----------------
__device__ __forceinline__ void off2_body(char* sm, const float4* __restrict__ t4,
                                          const float* __restrict__ ow,
                                          float* __restrict__ acc, int Hh, int Ww,
                                          int bxx, int byy, int bzz) {
    float* wsm = (float*)sm;
    float (*tile)[34][34] = (float(*)[34][34])(sm + 2304);
    int tx=threadIdx.x, ty=threadIdx.y, tid=ty*32+tx;
    int split = bzz & 7, b = bzz >> 3;
    int cb = split*32, gb = split*8;
    for (int i=tid;i<576;i+=256){int o=i/288,rem=i%288;wsm[i]=ow[(o*256+cb+rem/9)*9+rem%9];}
    size_t plane = (size_t)Hh*Ww;
    const float4* tb = t4 + (size_t)b*64*plane;
    int gx0 = bxx*32-1, gy0 = byy*32-1;
    float a0[4]={0,0,0,0}, a1[4]={0,0,0,0};
    for (int gg=0; gg<8; gg+=2) {
        __syncthreads();
        for (int i=tid;i<2*1156;i+=256){
            int g2=i/1156,pos=i%1156,yy=pos/34,xx=pos%34;
            int gy=gy0+yy, gx=gx0+xx;
            float4 v = make_float4(0.f,0.f,0.f,0.f);
            if (gy>=0&&gy<Hh&&gx>=0&&gx<Ww) v = tb[(size_t)(gb+gg+g2)*plane+(size_t)gy*Ww+gx];
            tile[g2*4+0][yy][xx]=v.x; tile[g2*4+1][yy][xx]=v.y;
            tile[g2*4+2][yy][xx]=v.z; tile[g2*4+3][yy][xx]=v.w;
        }
        __syncthreads();
        #pragma unroll
        for (int c8=0;c8<8;c8++){
            int lc = gg*4 + c8;
            float w0[9], w1[9];
            #pragma unroll
            for (int k=0;k<9;k++){w0[k]=wsm[lc*9+k];w1[k]=wsm[288+lc*9+k];}
            float vals[6][3];
            #pragma unroll
            for (int rr=0;rr<6;rr++)
                #pragma unroll
                for (int kx=0;kx<3;kx++) vals[rr][kx]=tile[c8][4*ty+rr][tx+kx];
            #pragma unroll
            for (int r=0;r<4;r++)
                #pragma unroll
                for (int ky=0;ky<3;ky++)
                    #pragma unroll
                    for (int kx=0;kx<3;kx++){
                        float v=vals[r+ky][kx];
                        a0[r]+=v*w0[ky*3+kx]; a1[r]+=v*w1[ky*3+kx];
                    }
        }
    }
    float* ob = acc + (((size_t)split*4 + b)*2)*plane;
    int px = bxx*32+tx;
    #pragma unroll
    for (int r=0;r<4;r++){
        int py = byy*32 + ty*4 + r;
        ob[(size_t)py*Ww+px]=a0[r];
        ob[plane+(size_t)py*Ww+px]=a1[r];
    }
}

__global__ void k_off2(const float4* __restrict__ t4, const float* __restrict__ ow,
                       float* __restrict__ acc, int Hh, int Ww) {
    __shared__ __align__(16) char sm[39296];
    off2_body(sm, t4, ow, acc, Hh, Ww, blockIdx.x, blockIdx.y, blockIdx.z);
}

__device__ __forceinline__ float reflect_clip(float v, float size) {
    float two = 2.f*size;
    float r = fmodf(v+0.5f, two);
    if (r < 0.f) r += two;
    if (r > size) r = two - r;
    r -= 0.5f;
    return fminf(fmaxf(r, 0.f), size-1.f);
}

__global__ void k_offfin(const float* __restrict__ acc, const float* __restrict__ ob,
                         float2* __restrict__ offmap, int Hh, int Ww) {
    int idx = blockIdx.x*blockDim.x + threadIdx.x;
    int n = BB*Hh*Ww;
    if (idx >= n) return;
    int px = idx % Ww; int t = idx / Ww;
    int py = t % Hh; int b = t / Hh;
    size_t plane = (size_t)Hh*Ww, pix = (size_t)py*Ww+px;
    float s0=0.f, s1=0.f;
    #pragma unroll
    for (int s=0;s<8;s++){
        const float* base = acc + (((size_t)s*4+b)*2)*plane + pix;
        s0 += base[0]; s1 += base[plane];
    }
    float offx = tanhf(s0 + ob[0]);
    float offy = tanhf(s1 + ob[1]);
    float w = (float)Ww, h = (float)Hh;
    float ix = ((float)px + offx) * (w/(w-1.f)) - 0.5f;
    float iy = ((float)py + offy) * (h/(h-1.f)) - 0.5f;
    offmap[(size_t)b*plane + pix] = make_float2(reflect_clip(ix, w), reflect_clip(iy, h));
}

// ---------------- sdp body (snake: gather->dw->relu->pw->wscale), packed state -----
__device__ __forceinline__ void sdp_body(char* sm, const float4* __restrict__ t4,
                                         const float2* __restrict__ offmap,
                                         const float* __restrict__ dww,
                                         const float* __restrict__ pww,
                                         const float* __restrict__ wsc,
                                         float4* __restrict__ outp, int Hh, int Ww,
                                         int bxx, int byy, int bzz) {
    float4* spk  = (float4*)sm;                        // 612*16 = 9792
    float4* sraw = (float4*)(sm + 9792);               // 13376 -> 23168
    float4* td   = (float4*)(sm + 23168);              // 9792 -> 32960
    float4* sdw4 = (float4*)(sm + 32960);              // 576
    float4* spw  = (float4*)(sm + 33536);              // 256
    float4* sws  = (float4*)(sm + 33792);              // 64 -> 33856 total
    int tx=threadIdx.x, ty=threadIdx.y, tid=ty*32+tx;
    int b = bzz >> 4, g0 = (bzz & 15)*G_PER;
    if (tid < G_PER*9) {
        int gi = tid/9, k = tid%9, c4 = (g0+gi)*4;
        sdw4[tid] = make_float4(dww[(c4+0)*9+k], dww[(c4+1)*9+k],
                                dww[(c4+2)*9+k], dww[(c4+3)*9+k]);
    }
    if (tid < G_PER*4) spw[tid] = *(const float4*)&pww[(g0*4+tid)*4];
    if (tid < G_PER)   sws[tid] = *(const float4*)&wsc[(g0+tid)*4];
    size_t plane = (size_t)Hh*Ww;
    const float2* ofp = offmap + (size_t)b*plane;
    int gx0 = bxx*32-1, gy0 = byy*16-1;
    int tx0 = gx0-2, ty0 = gy0-2;
    const float4* tb = t4 + (size_t)b*64*plane;
    {
        const float4* tg = tb + (size_t)g0*plane;
        for (int i=tid;i<NRAW;i+=256){
            int r=i/38, c=i%38;
            int gy=min(max(ty0+r,0),Hh-1), gx=min(max(tx0+c,0),Ww-1);
            __pipeline_memcpy_async(&sraw[i], &tg[(size_t)gy*Ww+gx], 16);
        }
        __pipeline_commit();
    }
    for (int i=tid;i<NHALO;i+=256)
        spk[i] = make_pack(i, ofp, gx0, gy0, tx0, ty0, Hh, Ww);
    int px = bxx*32+tx, py0 = byy*16 + 2*ty;
    __pipeline_wait_prior(0);
    __syncthreads();
    for (int gi=0; gi<G_PER; gi++) {
        int g = g0 + gi;
        for (int i=tid;i<NHALO;i+=256)
            td[i] = gather_one(spk[i], sraw);
        __syncthreads();
        if (gi+1 < G_PER){
            const float4* tg = tb + (size_t)(g+1)*plane;
            for (int i=tid;i<NRAW;i+=256){
                int r=i/38, c=i%38;
                int gy=min(max(ty0+r,0),Hh-1), gx=min(max(tx0+c,0),Ww-1);
                __pipeline_memcpy_async(&sraw[i], &tg[(size_t)gy*Ww+gx], 16);
            }
            __pipeline_commit();
        }
        float4 acc0=make_float4(0,0,0,0), acc1=make_float4(0,0,0,0);
        #pragma unroll
        for (int ky=0; ky<4; ky++){
            const float4* trow = &td[(2*ty+ky)*34 + tx];
            float4 v0=trow[0], v1=trow[1], v2=trow[2];
            if (ky < 3) {
                const float4* wr = &sdw4[gi*9 + ky*3];
                float4 w0=wr[0], w1=wr[1], w2=wr[2];
                acc0.x += v0.x*w0.x + v1.x*w1.x + v2.x*w2.x;
                acc0.y += v0.y*w0.y + v1.y*w1.y + v2.y*w2.y;
                acc0.z += v0.z*w0.z + v1.z*w1.z + v2.z*w2.z;
                acc0.w += v0.w*w0.w + v1.w*w1.w + v2.w*w2.w;
            }
            if (ky >= 1) {
                const float4* wr = &sdw4[gi*9 + (ky-1)*3];
                float4 w0=wr[0], w1=wr[1], w2=wr[2];
                acc1.x += v0.x*w0.x + v1.x*w1.x + v2.x*w2.x;
                acc1.y += v0.y*w0.y + v1.y*w1.y + v2.y*w2.y;
                acc1.z += v0.z*w0.z + v1.z*w1.z + v2.z*w2.z;
                acc1.w += v0.w*w0.w + v1.w*w1.w + v2.w*w2.w;
            }
        }
        float4 p0=spw[gi*4],p1=spw[gi*4+1],p2=spw[gi*4+2],p3=spw[gi*4+3],wsv=sws[gi];
        float4* og = outp + ((size_t)b*64+g)*plane;
        #pragma unroll
        for (int r=0;r<2;r++){
            float4 ac = r ? acc1 : acc0;
            float r0=fmaxf(ac.x,0.f), r1=fmaxf(ac.y,0.f);
            float r2=fmaxf(ac.z,0.f), r3=fmaxf(ac.w,0.f);
            float4 o;
            o.x=(r0*p0.x+r1*p0.y+r2*p0.z+r3*p0.w)*wsv.x;
            o.y=(r0*p1.x+r1*p1.y+r2*p1.z+r3*p1.w)*wsv.y;
            o.z=(r0*p2.x+r1*p2.y+r2*p2.z+r3*p2.w)*wsv.z;
            o.w=(r0*p3.x+r1*p3.y+r2*p3.z+r3*p3.w)*wsv.w;
            og[(size_t)(py0+r)*Ww + px] = o;
        }
        __pipeline_wait_prior(0);
        __syncthreads();
    }
}

// ---------------- merged kernel: even blocks = snake-L1, odd blocks = off2-L0 -------
__global__ void __launch_bounds__(256, 4)
k_mix(const float4* __restrict__ t1, const float2* __restrict__ off1,
      const float* __restrict__ dww1, const float* __restrict__ pww1,
      const float* __restrict__ wsc1, float4* __restrict__ tpw1,
      const float4* __restrict__ t0, const float* __restrict__ ow0,
      float* __restrict__ acc0) {
    __shared__ __align__(16) char sm[39296];
    int role = blockIdx.x & 1, idx = blockIdx.x >> 1;
    if (role == 0) {
        int bxx = idx & 1, byy = (idx >> 1) & 3, bzz = idx >> 3;
        sdp_body(sm, t1, off1, dww1, pww1, wsc1, tpw1, 64, 64, bxx, byy, bzz);
    } else {
        int bxx = idx & 3, byy = (idx >> 2) & 3, bzz = idx >> 4;
        off2_body(sm, t0, ow0, acc0, 128, 128, bxx, byy, bzz);
    }
}

// ---------------- level-0 snake + final reconstruction fused (GF=4, R12 version) ---
__global__ void __launch_bounds__(256, 4)
k_sdpfin(const float4* __restrict__ t4, const float2* __restrict__ offmap,
         const float* __restrict__ dww, const float* __restrict__ pww,
         const float* __restrict__ wsc, const float4* __restrict__ tpw1,
         const float* __restrict__ xin, const float* __restrict__ bw,
         const float* __restrict__ bb_, const float* __restrict__ bscale,
         const float* __restrict__ gammap, float* __restrict__ outp) {
    const int Hh=128, Ww=128;
    __shared__ __align__(16) float4 spack[NHALO];
    __shared__ __align__(16) float4 sraw[NRAW];
    __shared__ __align__(16) float4 td  [NHALO];
    __shared__ __align__(16) float sxf[34*SXPITCH];
    __shared__ float4 sdw4[GF*9];
    __shared__ float4 spw[GF*4];
    __shared__ float4 sws[GF];
    __shared__ float  sbw[GF*9];
    __shared__ float  sbb[GF], ssc[GF];
    int tx=threadIdx.x, ty=threadIdx.y, tid=ty*32+tx;
    int bx=blockIdx.x, by=blockIdx.y;
    int b = blockIdx.z >> 4, g0 = (blockIdx.z & 15)*GF;
    if (tid < GF*9) {
        int gi = tid/9, k = tid%9, c4 = (g0+gi)*4;
        sdw4[tid] = make_float4(dww[(c4+0)*9+k], dww[(c4+1)*9+k],
                                dww[(c4+2)*9+k], dww[(c4+3)*9+k]);
        sbw[tid] = bw[g0*9 + tid];
    }
    if (tid < GF*4) spw[tid] = *(const float4*)&pww[(g0*4+tid)*4];
    if (tid < GF) {
        sws[tid] = *(const float4*)&wsc[(g0+tid)*4];
        sbb[tid] = bb_[g0+tid];
        ssc[tid] = bscale[g0+tid];
    }
    float gm = __ldg(gammap);
    size_t plane = (size_t)Hh*Ww;
    const float2* ofp = offmap + (size_t)b*plane;
    int gx0 = bx*32-1, gy0 = by*16-1;
    int tx0 = gx0-2, ty0 = gy0-2;
    const float4* tb = t4 + (size_t)b*64*plane;
    {
        const float4* tg = tb + (size_t)g0*plane;
        for (int i=tid;i<NRAW;i+=256){
            int r=i/38, c=i%38;
            int gy=min(max(ty0+r,0),Hh-1), gx=min(max(tx0+c,0),Ww-1);
            __pipeline_memcpy_async(&sraw[i], &tg[(size_t)gy*Ww+gx], 16);
        }
        __pipeline_commit();
        const float* xg = xin + ((size_t)b*64+g0)*65536;
        for (int i=tid;i<NXT;i+=256){
            int sr=i/66, sc=i%66;
            int gy=32*by-1+sr, gxc=64*bx-1+sc;
            float* dst = &sxf[sr*SXPITCH+sc];
            if (gy>=0&&gy<256&&gxc>=0&&gxc<256)
                __pipeline_memcpy_async(dst, &xg[(size_t)gy*256+gxc], 4);
            else *dst = 0.f;
        }
        __pipeline_commit();
    }
    for (int i=tid;i<NHALO;i+=256)
        spack[i] = make_pack(i, ofp, gx0, gy0, tx0, ty0, Hh, Ww);
    int pxc = bx*32+tx, py0 = by*16 + 2*ty;
    __pipeline_wait_prior(0);
    __syncthreads();
    for (int gi=0; gi<GF; gi++) {
        int g = g0 + gi;
        for (int i=tid;i<NHALO;i+=256)
            td[i] = gather_one(spack[i], sraw);
        __syncthreads();
        if (gi+1 < GF){
            const float4* tg = tb + (size_t)(g+1)*plane;
            for (int i=tid;i<NRAW;i+=256){
                int r=i/38, c=i%38;
                int gy=min(max(ty0+r,0),Hh-1), gx=min(max(tx0+c,0),Ww-1);
                __pipeline_memcpy_async(&sraw[i], &tg[(size_t)gy*Ww+gx], 16);
            }
            __pipeline_commit();
        }
        float4 acc0=make_float4(0,0,0,0), acc1=make_float4(0,0,0,0);
        #pragma unroll
        for (int ky=0; ky<4; ky++){
            const float4* trow = &td[(2*ty+ky)*34 + tx];
            float4 v0=trow[0], v1=trow[1], v2=trow[2];
            if (ky < 3) {
                const float4* wr = &sdw4[gi*9 + ky*3];
                float4 w0=wr[0], w1=wr[1], w2=wr[2];
                acc0.x += v0.x*w0.x + v1.x*w1.x + v2.x*w2.x;
                acc0.y += v0.y*w0.y + v1.y*w1.y + v2.y*w2.y;
                acc0.z += v0.z*w0.z + v1.z*w1.z + v2.z*w2.z;
                acc0.w += v0.w*w0.w + v1.w*w1.w + v2.w*w2.w;
            }
            if (ky >= 1) {
                const float4* wr = &sdw4[gi*9 + (ky-1)*3];
                float4 w0=wr[0], w1=wr[1], w2=wr[2];
                acc1.x += v0.x*w0.x + v1.x*w1.x + v2.x*w2.x;
                acc1.y += v0.y*w0.y + v1.y*w1.y + v2.y*w2.y;
                acc1.z += v0.z*w0.z + v1.z*w1.z + v2.z*w2.z;
                acc1.w += v0.w*w0.w + v1.w*w1.w + v2.w*w2.w;
            }
        }
        float4 p0=spw[gi*4],p1=spw[gi*4+1],p2=spw[gi*4+2],p3=spw[gi*4+3],wsv=sws[gi];
        float4 o0, o1;
        {
            float r0=fmaxf(acc0.x,0.f), r1=fmaxf(acc0.y,0.f);
            float r2=fmaxf(acc0.z,0.f), r3=fmaxf(acc0.w,0.f);
            o0.x=(r0*p0.x+r1*p0.y+r2*p0.z+r3*p0.w)*wsv.x;
            o0.y=(r0*p1.x+r1*p1.y+r2*p1.z+r3*p1.w)*wsv.y;
            o0.z=(r0*p2.x+r1*p2.y+r2*p2.z+r3*p2.w)*wsv.z;
            o0.w=(r0*p3.x+r1*p3.y+r2*p3.z+r3*p3.w)*wsv.w;
            r0=fmaxf(acc1.x,0.f); r1=fmaxf(acc1.y,0.f);
            r2=fmaxf(acc1.z,0.f); r3=fmaxf(acc1.w,0.f);
            o1.x=(r0*p0.x+r1*p0.y+r2*p0.z+r3*p0.w)*wsv.x;
            o1.y=(r0*p1.x+r1*p1.y+r2*p1.z+r3*p1.w)*wsv.y;
            o1.z=(r0*p2.x+r1*p2.y+r2*p2.z+r3*p2.w)*wsv.z;
            o1.w=(r0*p3.x+r1*p3.y+r2*p3.z+r3*p3.w)*wsv.w;
        }
        if (gi+1 < GF) __pipeline_wait_prior(1);
        else           __pipeline_wait_prior(0);
        float4 n = tpw1[((size_t)(b*64+g)*64 + (py0>>1))*64 + (pxc>>1)];
        float sB = (pxc & 1) ? -1.f : 1.f;
        float nz = sB*n.z, nw = sB*n.w;
        float LL0 = o0.x + 0.5f*(n.x + n.y + nz + nw);
        float LL1 = o1.x + 0.5f*(n.x - n.y + nz - nw);
        float rec[4][2];
        rec[0][0]=0.5f*(LL0+o0.y+o0.z+o0.w); rec[0][1]=0.5f*(LL0+o0.y-o0.z-o0.w);
        rec[1][0]=0.5f*(LL0-o0.y+o0.z-o0.w); rec[1][1]=0.5f*(LL0-o0.y-o0.z+o0.w);
        rec[2][0]=0.5f*(LL1+o1.y+o1.z+o1.w); rec[2][1]=0.5f*(LL1+o1.y-o1.z-o1.w);
        rec[3][0]=0.5f*(LL1-o1.y+o1.z-o1.w); rec[3][1]=0.5f*(LL1-o1.y-o1.z+o1.w);
        float bw0=sbw[gi*9],bw1=sbw[gi*9+1],bw2=sbw[gi*9+2];
        float bw3=sbw[gi*9+3],bw4=sbw[gi*9+4],bw5=sbw[gi*9+5];
        float bw6=sbw[gi*9+6],bw7=sbw[gi*9+7],bw8=sbw[gi*9+8];
        float bias=sbb[gi], sc=ssc[gi];
        float* og = outp + ((size_t)b*64+g)*65536;
        int scol = 2*tx, srow0 = 4*ty;
        float r0c[4], r1c[4], r2c[4];
        #pragma unroll
        for (int k=0;k<4;k++){ r0c[k]=sxf[srow0*SXPITCH+scol+k];
                               r1c[k]=sxf[(srow0+1)*SXPITCH+scol+k]; }
        #pragma unroll
        for (int oi=0; oi<4; oi++){
            #pragma unroll
            for (int k=0;k<4;k++) r2c[k]=sxf[(srow0+oi+2)*SXPITCH+scol+k];
            float c0 = r0c[0]*bw0+r0c[1]*bw1+r0c[2]*bw2
                     + r1c[0]*bw3+r1c[1]*bw4+r1c[2]*bw5
                     + r2c[0]*bw6+r2c[1]*bw7+r2c[2]*bw8;
            float c1 = r0c[1]*bw0+r0c[2]*bw1+r0c[3]*bw2
                     + r1c[1]*bw3+r1c[2]*bw4+r1c[3]*bw5
                     + r2c[1]*bw6+r2c[2]*bw7+r2c[3]*bw8;
            int orow = 32*by + 4*ty + oi;
            float ov0 = (c0+bias)*sc + gm*rec[oi][0];
            float ov1 = (c1+bias)*sc + gm*rec[oi][1];
            *(float2*)&og[(size_t)orow*256 + 64*bx + 2*tx] = make_float2(ov0, ov1);
            #pragma unroll
            for (int k=0;k<4;k++){ r0c[k]=r1c[k]; r1c[k]=r2c[k]; }
        }
        __syncthreads();
        if (gi+1 < GF){
            const float* xg = xin + ((size_t)b*64+g+1)*65536;
            for (int i=tid;i<NXT;i+=256){
                int sr=i/66, sc=i%66;
                int gy=32*by-1+sr, gxc=64*bx-1+sc;
                float* dst = &sxf[sr*SXPITCH+sc];
                if (gy>=0&&gy<256&&gxc>=0&&gxc<256)
                    __pipeline_memcpy_async(dst, &xg[(size_t)gy*256+gxc], 4);
                else *dst = 0.f;
            }
            __pipeline_commit();
            __pipeline_wait_prior(1);
        }
        __syncthreads();
    }
}

extern "C" void kernel_launch(void* const* d_in, const int* in_sizes, int n_in,
                              void* d_out, int out_size) {
    const float* x       = (const float*)d_in[0];
    const float* base_w  = (const float*)d_in[1];
    const float* base_b  = (const float*)d_in[2];
    const float* base_sc = (const float*)d_in[3];
    const float* off_w   = (const float*)d_in[4];
    const float* off_b   = (const float*)d_in[5];
    const float* dw_w    = (const float*)d_in[6];
    const float* pw_w    = (const float*)d_in[7];
    const float* wscale  = (const float*)d_in[8];
    const float* gamma   = (const float*)d_in[9];
    float* out = (float*)d_out;

    float4 *t0, *t1, *tpw1;
    float *off0, *off1, *offacc;
    cudaGetSymbolAddress((void**)&t0,   g_t0);
    cudaGetSymbolAddress((void**)&t1,   g_t1);
    cudaGetSymbolAddress((void**)&tpw1, g_tpw1);
    cudaGetSymbolAddress((void**)&off0, g_off0);
    cudaGetSymbolAddress((void**)&off1, g_off1);
    cudaGetSymbolAddress((void**)&offacc, g_offacc);

    // both wavelet levels in one pass
    k_wt2<<<4096, 256>>>(x, t0, t1);
    // level-1 offsets
    k_off2<<<dim3(2,2,32), dim3(32,8)>>>(t1, off_w + 2*256*9, offacc, 64, 64);
    k_offfin<<<64, 256>>>(offacc, off_b + 2, (float2*)off1, 64, 64);
    // merged: level-1 snake (even blocks) + level-0 offset conv (odd blocks)
    k_mix<<<1024, dim3(32,8)>>>(t1, (const float2*)off1, dw_w + 256*9, pw_w + 256*4,
                                wscale + 256, tpw1, t0, off_w, offacc);
    // level-0 offset finalize
    k_offfin<<<256, 256>>>(offacc, off_b, (float2*)off0, 128, 128);
    // level-0 snake + full reconstruction + base, fused
    k_sdpfin<<<dim3(4,8,64), dim3(32,8)>>>(t0, (const float2*)off0, dw_w, pw_w, wscale,
                                           tpw1, x, base_w, base_b, base_sc, gamma, out);
}

// round 16
// speedup vs baseline: 1.1425x; 1.0894x over previous
#include <cuda_runtime.h>
#include <cuda_pipeline_primitives.h>
#include <math.h>

#define BB 4
#define CCH 64
#define G_PER 4            // snake groups/block (both levels)
#define GF    4            // fused final kernel groups/block
#define NHALO 612          // 34 x 18 halo points
#define NRAW  836          // 38 x 22 raw t tile
#define SXPITCH 72         // x-tile pitch: col3 = left edge, 4..67 aligned interior, 68 = right edge

__device__ __align__(16) float g_t0  [(size_t)4*64*128*128*4];
__device__ __align__(16) float g_t1  [(size_t)4*64*64*64*4];
__device__ __align__(16) float g_tpw1[(size_t)4*64*64*64*4];
__device__ __align__(8) float g_off0[(size_t)4*2*128*128];
__device__ __align__(8) float g_off1[(size_t)4*2*64*64];
__device__ float g_offacc[(size_t)8*4*2*128*128];

// Two-level Haar analysis fused, coalesced stores (proven shfl version).
__global__ void k_wt2(const float* __restrict__ src, float4* __restrict__ t0,
                      float4* __restrict__ t1) {
    int idx = blockIdx.x * blockDim.x + threadIdx.x;
    int q = idx & 127;
    int t = idx >> 7;
    int p = t & 31;
    t >>= 5;
    int c = t & 63; int b = t >> 6;
    const float* s = src + ((size_t)(b*64+c)*256 + 8*p)*256 + 2*q;
    float2 rowv[8];
    #pragma unroll
    for (int r=0;r<8;r++) rowv[r] = *(const float2*)(s + (size_t)r*256);
    float4* t0b = t0 + (size_t)(b*64+c)*128*128;
    float LL[4];
    #pragma unroll
    for (int rr=0; rr<4; rr++){
        float x00=rowv[2*rr].x, x01=rowv[2*rr].y;
        float x10=rowv[2*rr+1].x, x11=rowv[2*rr+1].y;
        float LLv=0.5f*(x00+x01+x10+x11), A=0.5f*(x00+x01-x10-x11);
        float Bv=0.5f*(x00-x01+x10-x11), Cv=0.5f*(x00-x01-x10+x11);
        t0b[(size_t)(4*p+rr)*128 + q] = make_float4(LLv,A,Bv,Cv);
        LL[rr]=LLv;
    }
    float LLp[4];
    #pragma unroll
    for (int rr=0;rr<4;rr++) LLp[rr] = __shfl_down_sync(0xffffffffu, LL[rr], 1);
    if (!(q & 1)) {
        float4* t1b = t1 + (size_t)(b*64+c)*64*64;
        #pragma unroll
        for (int jr=0;jr<2;jr++){
            float x00=LL[2*jr], x01=LLp[2*jr], x10=LL[2*jr+1], x11=LLp[2*jr+1];
            t1b[(size_t)(2*p+jr)*64 + (q>>1)] = make_float4(
                0.5f*(x00+x01+x10+x11), 0.5f*(x00+x01-x10-x11),
                0.5f*(x00-x01+x10-x11), 0.5f*(x00-x01-x10+x11));
        }
    }
}

// packed bilinear state: (i0, dx|dyo<<8, wx, wy); i0<0 => outside image (td=0)
__device__ __forceinline__ float4 make_pack(int i, const float2* __restrict__ ofp,
                                            int gx0, int gy0, int tx0, int ty0,
                                            int Hh, int Ww) {
    int xx=i%34, yy=i/34;
    int gx=gx0+xx, gy=gy0+yy;
    float4 pk = make_float4(__int_as_float(-1), 0.f, 0.f, 0.f);
    if (gx>=0&&gx<Ww&&gy>=0&&gy<Hh){
        float2 c = ofp[(size_t)gy*Ww+gx];
        float x0=floorf(c.x), y0=floorf(c.y);
        int x0i=(int)x0, y0i=(int)y0;
        int dx = min(x0i+1,Ww-1)-x0i;
        int dyo = (min(y0i+1,Hh-1)-y0i)*38;
        int i0 = (y0i-ty0)*38 + (x0i-tx0);
        pk = make_float4(__int_as_float(i0), __int_as_float(dx | (dyo<<8)),
                         c.x-x0, c.y-y0);
    }
    return pk;
}

__device__ __forceinline__ float4 gather_one(float4 pk, const float4* sraw) {
    int i0 = __float_as_int(pk.x);
    float4 r = make_float4(0.f,0.f,0.f,0.f);
    if (i0 >= 0) {
        int code = __float_as_int(pk.y);
        int dx = code & 0xff, dyo = code >> 8;
        float wx = pk.z, wy = pk.w;
        float u = 1.f-wx, v = 1.f-wy;
        float w00=v*u, w01=v*wx, w10=wy*u, w11=wy*wx;
        float4 a=sraw[i0], b=sraw[i0+dx], c=sraw[i0+dyo], d=sraw[i0+dyo+dx];
        r.x=a.x*w00+b.x*w01+c.x*w10+d.x*w11;
        r.y=a.y*w00+b.y*w01+c.y*w10+d.y*w11;
        r.z=a.z*w00+b.z*w01+c.z*w10+d.z*w11;
        r.w=a.w*w00+b.w*w01+c.w*w10+d.w*w11;
    }
    return r;
}

// ---------------- off2: pipelined dense 3x3 conv 256->2 (channel split) -------------
// one chunk = ONE group (4 channel planes); 2 buffers of 4x1156 floats each.
// smem: 2304 (weights) + 2*18496 (bufs) = 39296 B exactly.
__device__ __forceinline__ void off2_prefetch(float* buf, const float4* __restrict__ tb,
                                              int gidx, size_t plane,
                                              int gx0, int gy0, int Hh, int Ww, int tid) {
    const float4* tg = tb + (size_t)gidx*plane;
    for (int i=tid;i<1156;i+=256){
        int yy=i/34, xx=i%34;
        int gy=gy0+yy, gx=gx0+xx;
        float* d0=&buf[i];
        float* d1=&buf[1156+i];
        float* d2=&buf[2312+i];
        float* d3=&buf[3468+i];
        if (gy>=0&&gy<Hh&&gx>=0&&gx<Ww){
            const float* s=(const float*)&tg[(size_t)gy*Ww+gx];
            __pipeline_memcpy_async(d0,s+0,4);
            __pipeline_memcpy_async(d1,s+1,4);
            __pipeline_memcpy_async(d2,s+2,4);
            __pipeline_memcpy_async(d3,s+3,4);
        } else { *d0=0.f; *d1=0.f; *d2=0.f; *d3=0.f; }
    }
}

__device__ __forceinline__ void off2_body(char* sm, const float4* __restrict__ t4,
                                          const float* __restrict__ ow,
                                          float* __restrict__ acc, int Hh, int Ww,
                                          int bxx, int byy, int bzz) {
    float* wsm  = (float*)sm;                  // 576 floats = 2304B
    float* tile = (float*)(sm + 2304);         // 2 bufs x 4 planes x 1156 floats
    int tx=threadIdx.x, ty=threadIdx.y, tid=ty*32+tx;
    int split = bzz & 7, b = bzz >> 3;
    int cb = split*32, gb = split*8;
    for (int i=tid;i<576;i+=256){int o=i/288,rem=i%288;wsm[i]=ow[(o*256+cb+rem/9)*9+rem%9];}
    size_t plane = (size_t)Hh*Ww;
    const float4* tb = t4 + (size_t)b*64*plane;
    int gx0 = bxx*32-1, gy0 = byy*32-1;
    float a0[4]={0,0,0,0}, a1[4]={0,0,0,0};
    off2_prefetch(tile, tb, gb, plane, gx0, gy0, Hh, Ww, tid);
    __pipeline_commit();
    for (int ic=0; ic<8; ic++) {
        __pipeline_wait_prior(0);
        __syncthreads();
        if (ic+1 < 8){
            off2_prefetch(tile + ((ic+1)&1)*4624, tb, gb+ic+1, plane,
                          gx0, gy0, Hh, Ww, tid);
            __pipeline_commit();
        }
        const float* tbuf = tile + (ic&1)*4624;
        #pragma unroll
        for (int c4=0;c4<4;c4++){
            int lc = ic*4 + c4;
            float w0[9], w1[9];
            #pragma unroll
            for (int k=0;k<9;k++){w0[k]=wsm[lc*9+k];w1[k]=wsm[288+lc*9+k];}
            const float* tp = &tbuf[c4*1156];
            float vals[6][3];
            #pragma unroll
            for (int rr=0;rr<6;rr++)
                #pragma unroll
                for (int kx=0;kx<3;kx++) vals[rr][kx]=tp[(4*ty+rr)*34 + tx+kx];
            #pragma unroll
            for (int r=0;r<4;r++)
                #pragma unroll
                for (int ky=0;ky<3;ky++)
                    #pragma unroll
                    for (int kx=0;kx<3;kx++){
                        float v=vals[r+ky][kx];
                        a0[r]+=v*w0[ky*3+kx]; a1[r]+=v*w1[ky*3+kx];
                    }
        }
        __syncthreads();
    }
    float* ob = acc + (((size_t)split*4 + b)*2)*plane;
    int px = bxx*32+tx;
    #pragma unroll
    for (int r=0;r<4;r++){
        int py = byy*32 + ty*4 + r;
        ob[(size_t)py*Ww+px]=a0[r];
        ob[plane+(size_t)py*Ww+px]=a1[r];
    }
}

__global__ void k_off2(const float4* __restrict__ t4, const float* __restrict__ ow,
                       float* __restrict__ acc, int Hh, int Ww) {
    __shared__ __align__(16) char sm[39296];
    off2_body(sm, t4, ow, acc, Hh, Ww, blockIdx.x, blockIdx.y, blockIdx.z);
}

__device__ __forceinline__ float reflect_clip(float v, float size) {
    float two = 2.f*size;
    float r = fmodf(v+0.5f, two);
    if (r < 0.f) r += two;
    if (r > size) r = two - r;
    r -= 0.5f;
    return fminf(fmaxf(r, 0.f), size-1.f);
}

__global__ void k_offfin(const float* __restrict__ acc, const float* __restrict__ ob,
                         float2* __restrict__ offmap, int Hh, int Ww) {
    int idx = blockIdx.x*blockDim.x + threadIdx.x;
    int n = BB*Hh*Ww;
    if (idx >= n) return;
    int px = idx % Ww; int t = idx / Ww;
    int py = t % Hh; int b = t / Hh;
    size_t plane = (size_t)Hh*Ww, pix = (size_t)py*Ww+px;
    float s0=0.f, s1=0.f;
    #pragma unroll
    for (int s=0;s<8;s++){
        const float* base = acc + (((size_t)s*4+b)*2)*plane + pix;
        s0 += base[0]; s1 += base[plane];
    }
    float offx = tanhf(s0 + ob[0]);
    float offy = tanhf(s1 + ob[1]);
    float w = (float)Ww, h = (float)Hh;
    float ix = ((float)px + offx) * (w/(w-1.f)) - 0.5f;
    float iy = ((float)py + offy) * (h/(h-1.f)) - 0.5f;
    offmap[(size_t)b*plane + pix] = make_float2(reflect_clip(ix, w), reflect_clip(iy, h));
}

// ---------------- sdp body (snake: gather->dw->relu->pw->wscale), packed state -----
__device__ __forceinline__ void sdp_body(char* sm, const float4* __restrict__ t4,
                                         const float2* __restrict__ offmap,
                                         const float* __restrict__ dww,
                                         const float* __restrict__ pww,
                                         const float* __restrict__ wsc,
                                         float4* __restrict__ outp, int Hh, int Ww,
                                         int bxx, int byy, int bzz) {
    float4* spk  = (float4*)sm;                        // 9792
    float4* sraw = (float4*)(sm + 9792);               // 13376 -> 23168
    float4* td   = (float4*)(sm + 23168);              // 9792 -> 32960
    float4* sdw4 = (float4*)(sm + 32960);              // 576
    float4* spw  = (float4*)(sm + 33536);              // 256
    float4* sws  = (float4*)(sm + 33792);              // 64 -> 33856 total
    int tx=threadIdx.x, ty=threadIdx.y, tid=ty*32+tx;
    int b = bzz >> 4, g0 = (bzz & 15)*G_PER;
    if (tid < G_PER*9) {
        int gi = tid/9, k = tid%9, c4 = (g0+gi)*4;
        sdw4[tid] = make_float4(dww[(c4+0)*9+k], dww[(c4+1)*9+k],
                                dww[(c4+2)*9+k], dww[(c4+3)*9+k]);
    }
    if (tid < G_PER*4) spw[tid] = *(const float4*)&pww[(g0*4+tid)*4];
    if (tid < G_PER)   sws[tid] = *(const float4*)&wsc[(g0+tid)*4];
    size_t plane = (size_t)Hh*Ww;
    const float2* ofp = offmap + (size_t)b*plane;
    int gx0 = bxx*32-1, gy0 = byy*16-1;
    int tx0 = gx0-2, ty0 = gy0-2;
    const float4* tb = t4 + (size_t)b*64*plane;
    {
        const float4* tg = tb + (size_t)g0*plane;
        for (int i=tid;i<NRAW;i+=256){
            int r=i/38, c=i%38;
            int gy=min(max(ty0+r,0),Hh-1), gx=min(max(tx0+c,0),Ww-1);
            __pipeline_memcpy_async(&sraw[i], &tg[(size_t)gy*Ww+gx], 16);
        }
        __pipeline_commit();
    }
    for (int i=tid;i<NHALO;i+=256)
        spk[i] = make_pack(i, ofp, gx0, gy0, tx0, ty0, Hh, Ww);
    int px = bxx*32+tx, py0 = byy*16 + 2*ty;
    __pipeline_wait_prior(0);
    __syncthreads();
    for (int gi=0; gi<G_PER; gi++) {
        int g = g0 + gi;
        for (int i=tid;i<NHALO;i+=256)
            td[i] = gather_one(spk[i], sraw);
        __syncthreads();
        if (gi+1 < G_PER){
            const float4* tg = tb + (size_t)(g+1)*plane;
            for (int i=tid;i<NRAW;i+=256){
                int r=i/38, c=i%38;
                int gy=min(max(ty0+r,0),Hh-1), gx=min(max(tx0+c,0),Ww-1);
                __pipeline_memcpy_async(&sraw[i], &tg[(size_t)gy*Ww+gx], 16);
            }
            __pipeline_commit();
        }
        float4 acc0=make_float4(0,0,0,0), acc1=make_float4(0,0,0,0);
        #pragma unroll
        for (int ky=0; ky<4; ky++){
            const float4* trow = &td[(2*ty+ky)*34 + tx];
            float4 v0=trow[0], v1=trow[1], v2=trow[2];
            if (ky < 3) {
                const float4* wr = &sdw4[gi*9 + ky*3];
                float4 w0=wr[0], w1=wr[1], w2=wr[2];
                acc0.x += v0.x*w0.x + v1.x*w1.x + v2.x*w2.x;
                acc0.y += v0.y*w0.y + v1.y*w1.y + v2.y*w2.y;
                acc0.z += v0.z*w0.z + v1.z*w1.z + v2.z*w2.z;
                acc0.w += v0.w*w0.w + v1.w*w1.w + v2.w*w2.w;
            }
            if (ky >= 1) {
                const float4* wr = &sdw4[gi*9 + (ky-1)*3];
                float4 w0=wr[0], w1=wr[1], w2=wr[2];
                acc1.x += v0.x*w0.x + v1.x*w1.x + v2.x*w2.x;
                acc1.y += v0.y*w0.y + v1.y*w1.y + v2.y*w2.y;
                acc1.z += v0.z*w0.z + v1.z*w1.z + v2.z*w2.z;
                acc1.w += v0.w*w0.w + v1.w*w1.w + v2.w*w2.w;
            }
        }
        float4 p0=spw[gi*4],p1=spw[gi*4+1],p2=spw[gi*4+2],p3=spw[gi*4+3],wsv=sws[gi];
        float4* og = outp + ((size_t)b*64+g)*plane;
        #pragma unroll
        for (int r=0;r<2;r++){
            float4 ac = r ? acc1 : acc0;
            float r0=fmaxf(ac.x,0.f), r1=fmaxf(ac.y,0.f);
            float r2=fmaxf(ac.z,0.f), r3=fmaxf(ac.w,0.f);
            float4 o;
            o.x=(r0*p0.x+r1*p0.y+r2*p0.z+r3*p0.w)*wsv.x;
            o.y=(r0*p1.x+r1*p1.y+r2*p1.z+r3*p1.w)*wsv.y;
            o.z=(r0*p2.x+r1*p2.y+r2*p2.z+r3*p2.w)*wsv.z;
            o.w=(r0*p3.x+r1*p3.y+r2*p3.z+r3*p3.w)*wsv.w;
            og[(size_t)(py0+r)*Ww + px] = o;
        }
        __pipeline_wait_prior(0);
        __syncthreads();
    }
}

// ---------------- merged kernel: even blocks = snake-L1, odd blocks = off2-L0 -------
__global__ void __launch_bounds__(256, 4)
k_mix(const float4* __restrict__ t1, const float2* __restrict__ off1,
      const float* __restrict__ dww1, const float* __restrict__ pww1,
      const float* __restrict__ wsc1, float4* __restrict__ tpw1,
      const float4* __restrict__ t0, const float* __restrict__ ow0,
      float* __restrict__ acc0) {
    __shared__ __align__(16) char sm[39296];
    int role = blockIdx.x & 1, idx = blockIdx.x >> 1;
    if (role == 0) {
        int bxx = idx & 1, byy = (idx >> 1) & 3, bzz = idx >> 3;
        sdp_body(sm, t1, off1, dww1, pww1, wsc1, tpw1, 64, 64, bxx, byy, bzz);
    } else {
        int bxx = idx & 3, byy = (idx >> 2) & 3, bzz = idx >> 4;
        off2_body(sm, t0, ow0, acc0, 128, 128, bxx, byy, bzz);
    }
}

// stage a 34-row x-tile: aligned 16B interior (cols 4..67) + 4B edges (cols 3, 68)
__device__ __forceinline__ void stage_x(float* sxf, const float* __restrict__ xg,
                                        int bx, int by, int tid) {
    for (int i=tid;i<612;i+=256){
        if (i < 544){
            int sr=i>>4, k=i&15;
            int gy=32*by-1+sr;
            float* dst = &sxf[sr*SXPITCH + 4 + 4*k];
            if (gy>=0 && gy<256)
                __pipeline_memcpy_async(dst, &xg[(size_t)gy*256 + 64*bx + 4*k], 16);
            else { dst[0]=0.f; dst[1]=0.f; dst[2]=0.f; dst[3]=0.f; }
        } else {
            int e=i-544; int sr=e>>1, side=e&1;
            int gy=32*by-1+sr;
            int gxc = 64*bx - 1 + side*65;
            float* dst = &sxf[sr*SXPITCH + 3 + side*65];
            if (gy>=0 && gy<256 && gxc>=0 && gxc<256)
                __pipeline_memcpy_async(dst, &xg[(size_t)gy*256 + gxc], 4);
            else *dst = 0.f;
        }
    }
}

// ---------------- level-0 snake + final reconstruction fused (GF=4) ----------------
__global__ void __launch_bounds__(256, 4)
k_sdpfin(const float4* __restrict__ t4, const float2* __restrict__ offmap,
         const float* __restrict__ dww, const float* __restrict__ pww,
         const float* __restrict__ wsc, const float4* __restrict__ tpw1,
         const float* __restrict__ xin, const float* __restrict__ bw,
         const float* __restrict__ bb_, const float* __restrict__ bscale,
         const float* __restrict__ gammap, float* __restrict__ outp) {
    const int Hh=128, Ww=128;
    __shared__ __align__(16) float4 spack[NHALO];
    __shared__ __align__(16) float4 sraw[NRAW];
    __shared__ __align__(16) float4 td  [NHALO];
    __shared__ __align__(16) float sxf[34*SXPITCH];
    __shared__ float4 sdw4[GF*9];
    __shared__ float4 spw[GF*4];
    __shared__ float4 sws[GF];
    __shared__ float  sbw[GF*9];
    __shared__ float  sbb[GF], ssc[GF];
    int tx=threadIdx.x, ty=threadIdx.y, tid=ty*32+tx;
    int bx=blockIdx.x, by=blockIdx.y;
    int b = blockIdx.z >> 4, g0 = (blockIdx.z & 15)*GF;
    if (tid < GF*9) {
        int gi = tid/9, k = tid%9, c4 = (g0+gi)*4;
        sdw4[tid] = make_float4(dww[(c4+0)*9+k], dww[(c4+1)*9+k],
                                dww[(c4+2)*9+k], dww[(c4+3)*9+k]);
        sbw[tid] = bw[g0*9 + tid];
    }
    if (tid < GF*4) spw[tid] = *(const float4*)&pww[(g0*4+tid)*4];
    if (tid < GF) {
        sws[tid] = *(const float4*)&wsc[(g0+tid)*4];
        sbb[tid] = bb_[g0+tid];
        ssc[tid] = bscale[g0+tid];
    }
    float gm = __ldg(gammap);
    size_t plane = (size_t)Hh*Ww;
    const float2* ofp = offmap + (size_t)b*plane;
    int gx0 = bx*32-1, gy0 = by*16-1;
    int tx0 = gx0-2, ty0 = gy0-2;
    const float4* tb = t4 + (size_t)b*64*plane;
    {
        const float4* tg = tb + (size_t)g0*plane;
        for (int i=tid;i<NRAW;i+=256){
            int r=i/38, c=i%38;
            int gy=min(max(ty0+r,0),Hh-1), gx=min(max(tx0+c,0),Ww-1);
            __pipeline_memcpy_async(&sraw[i], &tg[(size_t)gy*Ww+gx], 16);
        }
        __pipeline_commit();
        stage_x(sxf, xin + ((size_t)b*64+g0)*65536, bx, by, tid);
        __pipeline_commit();
    }
    for (int i=tid;i<NHALO;i+=256)
        spack[i] = make_pack(i, ofp, gx0, gy0, tx0, ty0, Hh, Ww);
    int pxc = bx*32+tx, py0 = by*16 + 2*ty;
    __pipeline_wait_prior(0);
    __syncthreads();
    for (int gi=0; gi<GF; gi++) {
        int g = g0 + gi;
        for (int i=tid;i<NHALO;i+=256)
            td[i] = gather_one(spack[i], sraw);
        __syncthreads();
        if (gi+1 < GF){
            const float4* tg = tb + (size_t)(g+1)*plane;
            for (int i=tid;i<NRAW;i+=256){
                int r=i/38, c=i%38;
                int gy=min(max(ty0+r,0),Hh-1), gx=min(max(tx0+c,0),Ww-1);
                __pipeline_memcpy_async(&sraw[i], &tg[(size_t)gy*Ww+gx], 16);
            }
            __pipeline_commit();
        }
        float4 acc0=make_float4(0,0,0,0), acc1=make_float4(0,0,0,0);
        #pragma unroll
        for (int ky=0; ky<4; ky++){
            const float4* trow = &td[(2*ty+ky)*34 + tx];
            float4 v0=trow[0], v1=trow[1], v2=trow[2];
            if (ky < 3) {
                const float4* wr = &sdw4[gi*9 + ky*3];
                float4 w0=wr[0], w1=wr[1], w2=wr[2];
                acc0.x += v0.x*w0.x + v1.x*w1.x + v2.x*w2.x;
                acc0.y += v0.y*w0.y + v1.y*w1.y + v2.y*w2.y;
                acc0.z += v0.z*w0.z + v1.z*w1.z + v2.z*w2.z;
                acc0.w += v0.w*w0.w + v1.w*w1.w + v2.w*w2.w;
            }
            if (ky >= 1) {
                const float4* wr = &sdw4[gi*9 + (ky-1)*3];
                float4 w0=wr[0], w1=wr[1], w2=wr[2];
                acc1.x += v0.x*w0.x + v1.x*w1.x + v2.x*w2.x;
                acc1.y += v0.y*w0.y + v1.y*w1.y + v2.y*w2.y;
                acc1.z += v0.z*w0.z + v1.z*w1.z + v2.z*w2.z;
                acc1.w += v0.w*w0.w + v1.w*w1.w + v2.w*w2.w;
            }
        }
        float4 p0=spw[gi*4],p1=spw[gi*4+1],p2=spw[gi*4+2],p3=spw[gi*4+3],wsv=sws[gi];
        float4 o0, o1;
        {
            float r0=fmaxf(acc0.x,0.f), r1=fmaxf(acc0.y,0.f);
            float r2=fmaxf(acc0.z,0.f), r3=fmaxf(acc0.w,0.f);
            o0.x=(r0*p0.x+r1*p0.y+r2*p0.z+r3*p0.w)*wsv.x;
            o0.y=(r0*p1.x+r1*p1.y+r2*p1.z+r3*p1.w)*wsv.y;
            o0.z=(r0*p2.x+r1*p2.y+r2*p2.z+r3*p2.w)*wsv.z;
            o0.w=(r0*p3.x+r1*p3.y+r2*p3.z+r3*p3.w)*wsv.w;
            r0=fmaxf(acc1.x,0.f); r1=fmaxf(acc1.y,0.f);
            r2=fmaxf(acc1.z,0.f); r3=fmaxf(acc1.w,0.f);
            o1.x=(r0*p0.x+r1*p0.y+r2*p0.z+r3*p0.w)*wsv.x;
            o1.y=(r0*p1.x+r1*p1.y+r2*p1.z+r3*p1.w)*wsv.y;
            o1.z=(r0*p2.x+r1*p2.y+r2*p2.z+r3*p2.w)*wsv.z;
            o1.w=(r0*p3.x+r1*p3.y+r2*p3.z+r3*p3.w)*wsv.w;
        }
        if (gi+1 < GF) __pipeline_wait_prior(1);
        else           __pipeline_wait_prior(0);
        float4 n = tpw1[((size_t)(b*64+g)*64 + (py0>>1))*64 + (pxc>>1)];
        float sB = (pxc & 1) ? -1.f : 1.f;
        float nz = sB*n.z, nw = sB*n.w;
        float LL0 = o0.x + 0.5f*(n.x + n.y + nz + nw);
        float LL1 = o1.x + 0.5f*(n.x - n.y + nz - nw);
        float rec[4][2];
        rec[0][0]=0.5f*(LL0+o0.y+o0.z+o0.w); rec[0][1]=0.5f*(LL0+o0.y-o0.z-o0.w);
        rec[1][0]=0.5f*(LL0-o0.y+o0.z-o0.w); rec[1][1]=0.5f*(LL0-o0.y-o0.z+o0.w);
        rec[2][0]=0.5f*(LL1+o1.y+o1.z+o1.w); rec[2][1]=0.5f*(LL1+o1.y-o1.z-o1.w);
        rec[3][0]=0.5f*(LL1-o1.y+o1.z-o1.w); rec[3][1]=0.5f*(LL1-o1.y-o1.z+o1.w);
        float bw0=sbw[gi*9],bw1=sbw[gi*9+1],bw2=sbw[gi*9+2];
        float bw3=sbw[gi*9+3],bw4=sbw[gi*9+4],bw5=sbw[gi*9+5];
        float bw6=sbw[gi*9+6],bw7=sbw[gi*9+7],bw8=sbw[gi*9+8];
        float bias=sbb[gi], sc=ssc[gi];
        float* og = outp + ((size_t)b*64+g)*65536;
        int scol = 3 + 2*tx, srow0 = 4*ty;
        float r0c[4], r1c[4], r2c[4];
        #pragma unroll
        for (int k=0;k<4;k++){ r0c[k]=sxf[srow0*SXPITCH+scol+k];
                               r1c[k]=sxf[(srow0+1)*SXPITCH+scol+k]; }
        #pragma unroll
        for (int oi=0; oi<4; oi++){
            #pragma unroll
            for (int k=0;k<4;k++) r2c[k]=sxf[(srow0+oi+2)*SXPITCH+scol+k];
            float c0 = r0c[0]*bw0+r0c[1]*bw1+r0c[2]*bw2
                     + r1c[0]*bw3+r1c[1]*bw4+r1c[2]*bw5
                     + r2c[0]*bw6+r2c[1]*bw7+r2c[2]*bw8;
            float c1 = r0c[1]*bw0+r0c[2]*bw1+r0c[3]*bw2
                     + r1c[1]*bw3+r1c[2]*bw4+r1c[3]*bw5
                     + r2c[1]*bw6+r2c[2]*bw7+r2c[3]*bw8;
            int orow = 32*by + 4*ty + oi;
            float ov0 = (c0+bias)*sc + gm*rec[oi][0];
            float ov1 = (c1+bias)*sc + gm*rec[oi][1];
            *(float2*)&og[(size_t)orow*256 + 64*bx + 2*tx] = make_float2(ov0, ov1);
            #pragma unroll
            for (int k=0;k<4;k++){ r0c[k]=r1c[k]; r1c[k]=r2c[k]; }
        }
        __syncthreads();
        if (gi+1 < GF){
            stage_x(sxf, xin + ((size_t)b*64+g+1)*65536, bx, by, tid);
            __pipeline_commit();
            __pipeline_wait_prior(1);
        }
        __syncthreads();
    }
}

extern "C" void kernel_launch(void* const* d_in, const int* in_sizes, int n_in,
                              void* d_out, int out_size) {
    const float* x       = (const float*)d_in[0];
    const float* base_w  = (const float*)d_in[1];
    const float* base_b  = (const float*)d_in[2];
    const float* base_sc = (const float*)d_in[3];
    const float* off_w   = (const float*)d_in[4];
    const float* off_b   = (const float*)d_in[5];
    const float* dw_w    = (const float*)d_in[6];
    const float* pw_w    = (const float*)d_in[7];
    const float* wscale  = (const float*)d_in[8];
    const float* gamma   = (const float*)d_in[9];
    float* out = (float*)d_out;

    float4 *t0, *t1, *tpw1;
    float *off0, *off1, *offacc;
    cudaGetSymbolAddress((void**)&t0,   g_t0);
    cudaGetSymbolAddress((void**)&t1,   g_t1);
    cudaGetSymbolAddress((void**)&tpw1, g_tpw1);
    cudaGetSymbolAddress((void**)&off0, g_off0);
    cudaGetSymbolAddress((void**)&off1, g_off1);
    cudaGetSymbolAddress((void**)&offacc, g_offacc);

    // both wavelet levels in one pass
    k_wt2<<<4096, 256>>>(x, t0, t1);
    // level-1 offsets
    k_off2<<<dim3(2,2,32), dim3(32,8)>>>(t1, off_w + 2*256*9, offacc, 64, 64);
    k_offfin<<<64, 256>>>(offacc, off_b + 2, (float2*)off1, 64, 64);
    // merged: level-1 snake (even blocks) + level-0 offset conv (odd blocks)
    k_mix<<<1024, dim3(32,8)>>>(t1, (const float2*)off1, dw_w + 256*9, pw_w + 256*4,
                                wscale + 256, tpw1, t0, off_w, offacc);
    // level-0 offset finalize
    k_offfin<<<256, 256>>>(offacc, off_b, (float2*)off0, 128, 128);
    // level-0 snake + full reconstruction + base, fused
    k_sdpfin<<<dim3(4,8,64), dim3(32,8)>>>(t0, (const float2*)off0, dw_w, pw_w, wscale,
                                           tpw1, x, base_w, base_b, base_sc, gamma, out);
}

// round 17
// speedup vs baseline: 1.2188x; 1.0668x over previous
#include <cuda_runtime.h>
#include <cuda_pipeline_primitives.h>
#include <math.h>

#define BB 4
#define CCH 64
#define G_PER 4            // snake groups/block (both levels)
#define GF    4            // fused final kernel groups/block
#define NHALO 612          // 34 x 18 halo points
#define NRAW  836          // 38 x 22 raw t tile
#define SXPITCH 72         // x-tile pitch: col3 = left edge, 4..67 aligned interior, 68 = right edge

__device__ __align__(16) float g_t0  [(size_t)4*64*128*128*4];
__device__ __align__(16) float g_t1  [(size_t)4*64*64*64*4];
__device__ __align__(16) float g_tpw1[(size_t)4*64*64*64*4];
__device__ __align__(8) float g_off0[(size_t)4*2*128*128];
__device__ __align__(8) float g_off1[(size_t)4*2*64*64];
__device__ float g_offacc[(size_t)16*4*2*128*128];

// Two-level Haar analysis fused, coalesced stores (proven shfl version).
__global__ void k_wt2(const float* __restrict__ src, float4* __restrict__ t0,
                      float4* __restrict__ t1) {
    int idx = blockIdx.x * blockDim.x + threadIdx.x;
    int q = idx & 127;
    int t = idx >> 7;
    int p = t & 31;
    t >>= 5;
    int c = t & 63; int b = t >> 6;
    const float* s = src + ((size_t)(b*64+c)*256 + 8*p)*256 + 2*q;
    float2 rowv[8];
    #pragma unroll
    for (int r=0;r<8;r++) rowv[r] = *(const float2*)(s + (size_t)r*256);
    float4* t0b = t0 + (size_t)(b*64+c)*128*128;
    float LL[4];
    #pragma unroll
    for (int rr=0; rr<4; rr++){
        float x00=rowv[2*rr].x, x01=rowv[2*rr].y;
        float x10=rowv[2*rr+1].x, x11=rowv[2*rr+1].y;
        float LLv=0.5f*(x00+x01+x10+x11), A=0.5f*(x00+x01-x10-x11);
        float Bv=0.5f*(x00-x01+x10-x11), Cv=0.5f*(x00-x01-x10+x11);
        t0b[(size_t)(4*p+rr)*128 + q] = make_float4(LLv,A,Bv,Cv);
        LL[rr]=LLv;
    }
    float LLp[4];
    #pragma unroll
    for (int rr=0;rr<4;rr++) LLp[rr] = __shfl_down_sync(0xffffffffu, LL[rr], 1);
    if (!(q & 1)) {
        float4* t1b = t1 + (size_t)(b*64+c)*64*64;
        #pragma unroll
        for (int jr=0;jr<2;jr++){
            float x00=LL[2*jr], x01=LLp[2*jr], x10=LL[2*jr+1], x11=LLp[2*jr+1];
            t1b[(size_t)(2*p+jr)*64 + (q>>1)] = make_float4(
                0.5f*(x00+x01+x10+x11), 0.5f*(x00+x01-x10-x11),
                0.5f*(x00-x01+x10-x11), 0.5f*(x00-x01-x10+x11));
        }
    }
}

// packed bilinear state: (i0, dx|dyo<<8, wx, wy); i0<0 => outside image (td=0)
__device__ __forceinline__ float4 make_pack(int i, const float2* __restrict__ ofp,
                                            int gx0, int gy0, int tx0, int ty0,
                                            int Hh, int Ww) {
    int xx=i%34, yy=i/34;
    int gx=gx0+xx, gy=gy0+yy;
    float4 pk = make_float4(__int_as_float(-1), 0.f, 0.f, 0.f);
    if (gx>=0&&gx<Ww&&gy>=0&&gy<Hh){
        float2 c = ofp[(size_t)gy*Ww+gx];
        float x0=floorf(c.x), y0=floorf(c.y);
        int x0i=(int)x0, y0i=(int)y0;
        int dx = min(x0i+1,Ww-1)-x0i;
        int dyo = (min(y0i+1,Hh-1)-y0i)*38;
        int i0 = (y0i-ty0)*38 + (x0i-tx0);
        pk = make_float4(__int_as_float(i0), __int_as_float(dx | (dyo<<8)),
                         c.x-x0, c.y-y0);
    }
    return pk;
}

__device__ __forceinline__ float4 gather_one(float4 pk, const float4* sraw) {
    int i0 = __float_as_int(pk.x);
    float4 r = make_float4(0.f,0.f,0.f,0.f);
    if (i0 >= 0) {
        int code = __float_as_int(pk.y);
        int dx = code & 0xff, dyo = code >> 8;
        float wx = pk.z, wy = pk.w;
        float u = 1.f-wx, v = 1.f-wy;
        float w00=v*u, w01=v*wx, w10=wy*u, w11=wy*wx;
        float4 a=sraw[i0], b=sraw[i0+dx], c=sraw[i0+dyo], d=sraw[i0+dyo+dx];
        r.x=a.x*w00+b.x*w01+c.x*w10+d.x*w11;
        r.y=a.y*w00+b.y*w01+c.y*w10+d.y*w11;
        r.z=a.z*w00+b.z*w01+c.z*w10+d.z*w11;
        r.w=a.w*w00+b.w*w01+c.w*w10+d.w*w11;
    }
    return r;
}

// ---------------- off2: dense 3x3 conv 256->2, 16-way channel split ----------------
// 16 ch/block (4 groups), 2 chunks of 2 groups into one 8-plane tile buffer.
// smem: 1280 (weights, aligned) + 8*34*34*4 = 38272 B.
__device__ __forceinline__ void off2_body(char* sm, const float4* __restrict__ t4,
                                          const float* __restrict__ ow,
                                          float* __restrict__ acc, int Hh, int Ww,
                                          int bxx, int byy, int bzz) {
    float* wsm = (float*)sm;                               // 288 floats
    float (*tile)[34][34] = (float(*)[34][34])(sm + 1280); // 8 x 34 x 34
    int tx=threadIdx.x, ty=threadIdx.y, tid=ty*32+tx;
    int split = bzz & 15, b = bzz >> 4;
    int cb = split*16, gb = split*4;
    for (int i=tid;i<288;i+=256){int o=i/144,rem=i%144;wsm[i]=ow[(o*256+cb+rem/9)*9+rem%9];}
    size_t plane = (size_t)Hh*Ww;
    const float4* tb = t4 + (size_t)b*64*plane;
    int gx0 = bxx*32-1, gy0 = byy*32-1;
    float a0[4]={0,0,0,0}, a1[4]={0,0,0,0};
    for (int gg=0; gg<4; gg+=2) {
        __syncthreads();
        for (int i=tid;i<2*1156;i+=256){
            int g2=i/1156,pos=i%1156,yy=pos/34,xx=pos%34;
            int gy=gy0+yy, gx=gx0+xx;
            float4 v = make_float4(0.f,0.f,0.f,0.f);
            if (gy>=0&&gy<Hh&&gx>=0&&gx<Ww) v = tb[(size_t)(gb+gg+g2)*plane+(size_t)gy*Ww+gx];
            tile[g2*4+0][yy][xx]=v.x; tile[g2*4+1][yy][xx]=v.y;
            tile[g2*4+2][yy][xx]=v.z; tile[g2*4+3][yy][xx]=v.w;
        }
        __syncthreads();
        #pragma unroll
        for (int c8=0;c8<8;c8++){
            int lc = gg*4 + c8;
            float w0[9], w1[9];
            #pragma unroll
            for (int k=0;k<9;k++){w0[k]=wsm[lc*9+k];w1[k]=wsm[144+lc*9+k];}
            float vals[6][3];
            #pragma unroll
            for (int rr=0;rr<6;rr++)
                #pragma unroll
                for (int kx=0;kx<3;kx++) vals[rr][kx]=tile[c8][4*ty+rr][tx+kx];
            #pragma unroll
            for (int r=0;r<4;r++)
                #pragma unroll
                for (int ky=0;ky<3;ky++)
                    #pragma unroll
                    for (int kx=0;kx<3;kx++){
                        float v=vals[r+ky][kx];
                        a0[r]+=v*w0[ky*3+kx]; a1[r]+=v*w1[ky*3+kx];
                    }
        }
    }
    float* ob = acc + (((size_t)split*4 + b)*2)*plane;
    int px = bxx*32+tx;
    #pragma unroll
    for (int r=0;r<4;r++){
        int py = byy*32 + ty*4 + r;
        ob[(size_t)py*Ww+px]=a0[r];
        ob[plane+(size_t)py*Ww+px]=a1[r];
    }
}

__global__ void k_off2(const float4* __restrict__ t4, const float* __restrict__ ow,
                       float* __restrict__ acc, int Hh, int Ww) {
    __shared__ __align__(16) char sm[39296];
    off2_body(sm, t4, ow, acc, Hh, Ww, blockIdx.x, blockIdx.y, blockIdx.z);
}

__device__ __forceinline__ float reflect_clip(float v, float size) {
    float two = 2.f*size;
    float r = fmodf(v+0.5f, two);
    if (r < 0.f) r += two;
    if (r > size) r = two - r;
    r -= 0.5f;
    return fminf(fmaxf(r, 0.f), size-1.f);
}

// sum 16 partials + bias -> tanh -> reflect-clipped coords, packed float2
__global__ void k_offfin(const float* __restrict__ acc, const float* __restrict__ ob,
                         float2* __restrict__ offmap, int Hh, int Ww) {
    int idx = blockIdx.x*blockDim.x + threadIdx.x;
    int n = BB*Hh*Ww;
    if (idx >= n) return;
    int px = idx % Ww; int t = idx / Ww;
    int py = t % Hh; int b = t / Hh;
    size_t plane = (size_t)Hh*Ww, pix = (size_t)py*Ww+px;
    float s0=0.f, s1=0.f;
    #pragma unroll
    for (int s=0;s<16;s++){
        const float* base = acc + (((size_t)s*4+b)*2)*plane + pix;
        s0 += base[0]; s1 += base[plane];
    }
    float offx = tanhf(s0 + ob[0]);
    float offy = tanhf(s1 + ob[1]);
    float w = (float)Ww, h = (float)Hh;
    float ix = ((float)px + offx) * (w/(w-1.f)) - 0.5f;
    float iy = ((float)py + offy) * (h/(h-1.f)) - 0.5f;
    offmap[(size_t)b*plane + pix] = make_float2(reflect_clip(ix, w), reflect_clip(iy, h));
}

// ---------------- sdp body (snake: gather->dw->relu->pw->wscale), packed state -----
__device__ __forceinline__ void sdp_body(char* sm, const float4* __restrict__ t4,
                                         const float2* __restrict__ offmap,
                                         const float* __restrict__ dww,
                                         const float* __restrict__ pww,
                                         const float* __restrict__ wsc,
                                         float4* __restrict__ outp, int Hh, int Ww,
                                         int bxx, int byy, int bzz) {
    float4* spk  = (float4*)sm;                        // 9792
    float4* sraw = (float4*)(sm + 9792);               // 13376 -> 23168
    float4* td   = (float4*)(sm + 23168);              // 9792 -> 32960
    float4* sdw4 = (float4*)(sm + 32960);              // 576
    float4* spw  = (float4*)(sm + 33536);              // 256
    float4* sws  = (float4*)(sm + 33792);              // 64 -> 33856 total
    int tx=threadIdx.x, ty=threadIdx.y, tid=ty*32+tx;
    int b = bzz >> 4, g0 = (bzz & 15)*G_PER;
    if (tid < G_PER*9) {
        int gi = tid/9, k = tid%9, c4 = (g0+gi)*4;
        sdw4[tid] = make_float4(dww[(c4+0)*9+k], dww[(c4+1)*9+k],
                                dww[(c4+2)*9+k], dww[(c4+3)*9+k]);
    }
    if (tid < G_PER*4) spw[tid] = *(const float4*)&pww[(g0*4+tid)*4];
    if (tid < G_PER)   sws[tid] = *(const float4*)&wsc[(g0+tid)*4];
    size_t plane = (size_t)Hh*Ww;
    const float2* ofp = offmap + (size_t)b*plane;
    int gx0 = bxx*32-1, gy0 = byy*16-1;
    int tx0 = gx0-2, ty0 = gy0-2;
    const float4* tb = t4 + (size_t)b*64*plane;
    {
        const float4* tg = tb + (size_t)g0*plane;
        for (int i=tid;i<NRAW;i+=256){
            int r=i/38, c=i%38;
            int gy=min(max(ty0+r,0),Hh-1), gx=min(max(tx0+c,0),Ww-1);
            __pipeline_memcpy_async(&sraw[i], &tg[(size_t)gy*Ww+gx], 16);
        }
        __pipeline_commit();
    }
    for (int i=tid;i<NHALO;i+=256)
        spk[i] = make_pack(i, ofp, gx0, gy0, tx0, ty0, Hh, Ww);
    int px = bxx*32+tx, py0 = byy*16 + 2*ty;
    __pipeline_wait_prior(0);
    __syncthreads();
    for (int gi=0; gi<G_PER; gi++) {
        int g = g0 + gi;
        for (int i=tid;i<NHALO;i+=256)
            td[i] = gather_one(spk[i], sraw);
        __syncthreads();
        if (gi+1 < G_PER){
            const float4* tg = tb + (size_t)(g+1)*plane;
            for (int i=tid;i<NRAW;i+=256){
                int r=i/38, c=i%38;
                int gy=min(max(ty0+r,0),Hh-1), gx=min(max(tx0+c,0),Ww-1);
                __pipeline_memcpy_async(&sraw[i], &tg[(size_t)gy*Ww+gx], 16);
            }
            __pipeline_commit();
        }
        float4 acc0=make_float4(0,0,0,0), acc1=make_float4(0,0,0,0);
        #pragma unroll
        for (int ky=0; ky<4; ky++){
            const float4* trow = &td[(2*ty+ky)*34 + tx];
            float4 v0=trow[0], v1=trow[1], v2=trow[2];
            if (ky < 3) {
                const float4* wr = &sdw4[gi*9 + ky*3];
                float4 w0=wr[0], w1=wr[1], w2=wr[2];
                acc0.x += v0.x*w0.x + v1.x*w1.x + v2.x*w2.x;
                acc0.y += v0.y*w0.y + v1.y*w1.y + v2.y*w2.y;
                acc0.z += v0.z*w0.z + v1.z*w1.z + v2.z*w2.z;
                acc0.w += v0.w*w0.w + v1.w*w1.w + v2.w*w2.w;
            }
            if (ky >= 1) {
                const float4* wr = &sdw4[gi*9 + (ky-1)*3];
                float4 w0=wr[0], w1=wr[1], w2=wr[2];
                acc1.x += v0.x*w0.x + v1.x*w1.x + v2.x*w2.x;
                acc1.y += v0.y*w0.y + v1.y*w1.y + v2.y*w2.y;
                acc1.z += v0.z*w0.z + v1.z*w1.z + v2.z*w2.z;
                acc1.w += v0.w*w0.w + v1.w*w1.w + v2.w*w2.w;
            }
        }
        float4 p0=spw[gi*4],p1=spw[gi*4+1],p2=spw[gi*4+2],p3=spw[gi*4+3],wsv=sws[gi];
        float4* og = outp + ((size_t)b*64+g)*plane;
        #pragma unroll
        for (int r=0;r<2;r++){
            float4 ac = r ? acc1 : acc0;
            float r0=fmaxf(ac.x,0.f), r1=fmaxf(ac.y,0.f);
            float r2=fmaxf(ac.z,0.f), r3=fmaxf(ac.w,0.f);
            float4 o;
            o.x=(r0*p0.x+r1*p0.y+r2*p0.z+r3*p0.w)*wsv.x;
            o.y=(r0*p1.x+r1*p1.y+r2*p1.z+r3*p1.w)*wsv.y;
            o.z=(r0*p2.x+r1*p2.y+r2*p2.z+r3*p2.w)*wsv.z;
            o.w=(r0*p3.x+r1*p3.y+r2*p3.z+r3*p3.w)*wsv.w;
            og[(size_t)(py0+r)*Ww + px] = o;
        }
        __pipeline_wait_prior(0);
        __syncthreads();
    }
}

// ---------------- merged kernel: bid%3==0 -> snake-L1 (512), else off2-L0 (1024) ----
__global__ void __launch_bounds__(256, 4)
k_mix(const float4* __restrict__ t1, const float2* __restrict__ off1,
      const float* __restrict__ dww1, const float* __restrict__ pww1,
      const float* __restrict__ wsc1, float4* __restrict__ tpw1,
      const float4* __restrict__ t0, const float* __restrict__ ow0,
      float* __restrict__ acc0) {
    __shared__ __align__(16) char sm[39296];
    int bid = blockIdx.x;
    int q = bid / 3, r = bid % 3;
    if (r == 0) {
        int idx = q;                           // [0,512)
        int bxx = idx & 1, byy = (idx >> 1) & 3, bzz = idx >> 3;
        sdp_body(sm, t1, off1, dww1, pww1, wsc1, tpw1, 64, 64, bxx, byy, bzz);
    } else {
        int idx = 2*q + (r-1);                 // [0,1024)
        int bxx = idx & 3, byy = (idx >> 2) & 3, bzz = idx >> 4;
        off2_body(sm, t0, ow0, acc0, 128, 128, bxx, byy, bzz);
    }
}

// stage a 34-row x-tile: aligned 16B interior (cols 4..67) + 4B edges (cols 3, 68)
__device__ __forceinline__ void stage_x(float* sxf, const float* __restrict__ xg,
                                        int bx, int by, int tid) {
    for (int i=tid;i<612;i+=256){
        if (i < 544){
            int sr=i>>4, k=i&15;
            int gy=32*by-1+sr;
            float* dst = &sxf[sr*SXPITCH + 4 + 4*k];
            if (gy>=0 && gy<256)
                __pipeline_memcpy_async(dst, &xg[(size_t)gy*256 + 64*bx + 4*k], 16);
            else { dst[0]=0.f; dst[1]=0.f; dst[2]=0.f; dst[3]=0.f; }
        } else {
            int e=i-544; int sr=e>>1, side=e&1;
            int gy=32*by-1+sr;
            int gxc = 64*bx - 1 + side*65;
            float* dst = &sxf[sr*SXPITCH + 3 + side*65];
            if (gy>=0 && gy<256 && gxc>=0 && gxc<256)
                __pipeline_memcpy_async(dst, &xg[(size_t)gy*256 + gxc], 4);
            else *dst = 0.f;
        }
    }
}

// ---------------- level-0 snake + final reconstruction fused (GF=4) ----------------
__global__ void __launch_bounds__(256, 4)
k_sdpfin(const float4* __restrict__ t4, const float2* __restrict__ offmap,
         const float* __restrict__ dww, const float* __restrict__ pww,
         const float* __restrict__ wsc, const float4* __restrict__ tpw1,
         const float* __restrict__ xin, const float* __restrict__ bw,
         const float* __restrict__ bb_, const float* __restrict__ bscale,
         const float* __restrict__ gammap, float* __restrict__ outp) {
    const int Hh=128, Ww=128;
    __shared__ __align__(16) float4 spack[NHALO];
    __shared__ __align__(16) float4 sraw[NRAW];
    __shared__ __align__(16) float4 td  [NHALO];
    __shared__ __align__(16) float sxf[34*SXPITCH];
    __shared__ float4 sdw4[GF*9];
    __shared__ float4 spw[GF*4];
    __shared__ float4 sws[GF];
    __shared__ float  sbw[GF*9];
    __shared__ float  sbb[GF], ssc[GF];
    int tx=threadIdx.x, ty=threadIdx.y, tid=ty*32+tx;
    int bx=blockIdx.x, by=blockIdx.y;
    int b = blockIdx.z >> 4, g0 = (blockIdx.z & 15)*GF;
    if (tid < GF*9) {
        int gi = tid/9, k = tid%9, c4 = (g0+gi)*4;
        sdw4[tid] = make_float4(dww[(c4+0)*9+k], dww[(c4+1)*9+k],
                                dww[(c4+2)*9+k], dww[(c4+3)*9+k]);
        sbw[tid] = bw[g0*9 + tid];
    }
    if (tid < GF*4) spw[tid] = *(const float4*)&pww[(g0*4+tid)*4];
    if (tid < GF) {
        sws[tid] = *(const float4*)&wsc[(g0+tid)*4];
        sbb[tid] = bb_[g0+tid];
        ssc[tid] = bscale[g0+tid];
    }
    float gm = __ldg(gammap);
    size_t plane = (size_t)Hh*Ww;
    const float2* ofp = offmap + (size_t)b*plane;
    int gx0 = bx*32-1, gy0 = by*16-1;
    int tx0 = gx0-2, ty0 = gy0-2;
    const float4* tb = t4 + (size_t)b*64*plane;
    {
        const float4* tg = tb + (size_t)g0*plane;
        for (int i=tid;i<NRAW;i+=256){
            int r=i/38, c=i%38;
            int gy=min(max(ty0+r,0),Hh-1), gx=min(max(tx0+c,0),Ww-1);
            __pipeline_memcpy_async(&sraw[i], &tg[(size_t)gy*Ww+gx], 16);
        }
        __pipeline_commit();
        stage_x(sxf, xin + ((size_t)b*64+g0)*65536, bx, by, tid);
        __pipeline_commit();
    }
    for (int i=tid;i<NHALO;i+=256)
        spack[i] = make_pack(i, ofp, gx0, gy0, tx0, ty0, Hh, Ww);
    int pxc = bx*32+tx, py0 = by*16 + 2*ty;
    __pipeline_wait_prior(0);
    __syncthreads();
    for (int gi=0; gi<GF; gi++) {
        int g = g0 + gi;
        for (int i=tid;i<NHALO;i+=256)
            td[i] = gather_one(spack[i], sraw);
        __syncthreads();
        if (gi+1 < GF){
            const float4* tg = tb + (size_t)(g+1)*plane;
            for (int i=tid;i<NRAW;i+=256){
                int r=i/38, c=i%38;
                int gy=min(max(ty0+r,0),Hh-1), gx=min(max(tx0+c,0),Ww-1);
                __pipeline_memcpy_async(&sraw[i], &tg[(size_t)gy*Ww+gx], 16);
            }
            __pipeline_commit();
        }
        float4 acc0=make_float4(0,0,0,0), acc1=make_float4(0,0,0,0);
        #pragma unroll
        for (int ky=0; ky<4; ky++){
            const float4* trow = &td[(2*ty+ky)*34 + tx];
            float4 v0=trow[0], v1=trow[1], v2=trow[2];
            if (ky < 3) {
                const float4* wr = &sdw4[gi*9 + ky*3];
                float4 w0=wr[0], w1=wr[1], w2=wr[2];
                acc0.x += v0.x*w0.x + v1.x*w1.x + v2.x*w2.x;
                acc0.y += v0.y*w0.y + v1.y*w1.y + v2.y*w2.y;
                acc0.z += v0.z*w0.z + v1.z*w1.z + v2.z*w2.z;
                acc0.w += v0.w*w0.w + v1.w*w1.w + v2.w*w2.w;
            }
            if (ky >= 1) {
                const float4* wr = &sdw4[gi*9 + (ky-1)*3];
                float4 w0=wr[0], w1=wr[1], w2=wr[2];
                acc1.x += v0.x*w0.x + v1.x*w1.x + v2.x*w2.x;
                acc1.y += v0.y*w0.y + v1.y*w1.y + v2.y*w2.y;
                acc1.z += v0.z*w0.z + v1.z*w1.z + v2.z*w2.z;
                acc1.w += v0.w*w0.w + v1.w*w1.w + v2.w*w2.w;
            }
        }
        float4 p0=spw[gi*4],p1=spw[gi*4+1],p2=spw[gi*4+2],p3=spw[gi*4+3],wsv=sws[gi];
        float4 o0, o1;
        {
            float r0=fmaxf(acc0.x,0.f), r1=fmaxf(acc0.y,0.f);
            float r2=fmaxf(acc0.z,0.f), r3=fmaxf(acc0.w,0.f);
            o0.x=(r0*p0.x+r1*p0.y+r2*p0.z+r3*p0.w)*wsv.x;
            o0.y=(r0*p1.x+r1*p1.y+r2*p1.z+r3*p1.w)*wsv.y;
            o0.z=(r0*p2.x+r1*p2.y+r2*p2.z+r3*p2.w)*wsv.z;
            o0.w=(r0*p3.x+r1*p3.y+r2*p3.z+r3*p3.w)*wsv.w;
            r0=fmaxf(acc1.x,0.f); r1=fmaxf(acc1.y,0.f);
            r2=fmaxf(acc1.z,0.f); r3=fmaxf(acc1.w,0.f);
            o1.x=(r0*p0.x+r1*p0.y+r2*p0.z+r3*p0.w)*wsv.x;
            o1.y=(r0*p1.x+r1*p1.y+r2*p1.z+r3*p1.w)*wsv.y;
            o1.z=(r0*p2.x+r1*p2.y+r2*p2.z+r3*p2.w)*wsv.z;
            o1.w=(r0*p3.x+r1*p3.y+r2*p3.z+r3*p3.w)*wsv.w;
        }
        if (gi+1 < GF) __pipeline_wait_prior(1);
        else           __pipeline_wait_prior(0);
        float4 n = tpw1[((size_t)(b*64+g)*64 + (py0>>1))*64 + (pxc>>1)];
        float sB = (pxc & 1) ? -1.f : 1.f;
        float nz = sB*n.z, nw = sB*n.w;
        float LL0 = o0.x + 0.5f*(n.x + n.y + nz + nw);
        float LL1 = o1.x + 0.5f*(n.x - n.y + nz - nw);
        float rec[4][2];
        rec[0][0]=0.5f*(LL0+o0.y+o0.z+o0.w); rec[0][1]=0.5f*(LL0+o0.y-o0.z-o0.w);
        rec[1][0]=0.5f*(LL0-o0.y+o0.z-o0.w); rec[1][1]=0.5f*(LL0-o0.y-o0.z+o0.w);
        rec[2][0]=0.5f*(LL1+o1.y+o1.z+o1.w); rec[2][1]=0.5f*(LL1+o1.y-o1.z-o1.w);
        rec[3][0]=0.5f*(LL1-o1.y+o1.z-o1.w); rec[3][1]=0.5f*(LL1-o1.y-o1.z+o1.w);
        float bw0=sbw[gi*9],bw1=sbw[gi*9+1],bw2=sbw[gi*9+2];
        float bw3=sbw[gi*9+3],bw4=sbw[gi*9+4],bw5=sbw[gi*9+5];
        float bw6=sbw[gi*9+6],bw7=sbw[gi*9+7],bw8=sbw[gi*9+8];
        float bias=sbb[gi], sc=ssc[gi];
        float* og = outp + ((size_t)b*64+g)*65536;
        int scol = 3 + 2*tx, srow0 = 4*ty;
        float r0c[4], r1c[4], r2c[4];
        #pragma unroll
        for (int k=0;k<4;k++){ r0c[k]=sxf[srow0*SXPITCH+scol+k];
                               r1c[k]=sxf[(srow0+1)*SXPITCH+scol+k]; }
        #pragma unroll
        for (int oi=0; oi<4; oi++){
            #pragma unroll
            for (int k=0;k<4;k++) r2c[k]=sxf[(srow0+oi+2)*SXPITCH+scol+k];
            float c0 = r0c[0]*bw0+r0c[1]*bw1+r0c[2]*bw2
                     + r1c[0]*bw3+r1c[1]*bw4+r1c[2]*bw5
                     + r2c[0]*bw6+r2c[1]*bw7+r2c[2]*bw8;
            float c1 = r0c[1]*bw0+r0c[2]*bw1+r0c[3]*bw2
                     + r1c[1]*bw3+r1c[2]*bw4+r1c[3]*bw5
                     + r2c[1]*bw6+r2c[2]*bw7+r2c[3]*bw8;
            int orow = 32*by + 4*ty + oi;
            float ov0 = (c0+bias)*sc + gm*rec[oi][0];
            float ov1 = (c1+bias)*sc + gm*rec[oi][1];
            *(float2*)&og[(size_t)orow*256 + 64*bx + 2*tx] = make_float2(ov0, ov1);
            #pragma unroll
            for (int k=0;k<4;k++){ r0c[k]=r1c[k]; r1c[k]=r2c[k]; }
        }
        __syncthreads();
        if (gi+1 < GF){
            stage_x(sxf, xin + ((size_t)b*64+g+1)*65536, bx, by, tid);
            __pipeline_commit();
            __pipeline_wait_prior(1);
        }
        __syncthreads();
    }
}

extern "C" void kernel_launch(void* const* d_in, const int* in_sizes, int n_in,
                              void* d_out, int out_size) {
    const float* x       = (const float*)d_in[0];
    const float* base_w  = (const float*)d_in[1];
    const float* base_b  = (const float*)d_in[2];
    const float* base_sc = (const float*)d_in[3];
    const float* off_w   = (const float*)d_in[4];
    const float* off_b   = (const float*)d_in[5];
    const float* dw_w    = (const float*)d_in[6];
    const float* pw_w    = (const float*)d_in[7];
    const float* wscale  = (const float*)d_in[8];
    const float* gamma   = (const float*)d_in[9];
    float* out = (float*)d_out;

    float4 *t0, *t1, *tpw1;
    float *off0, *off1, *offacc;
    cudaGetSymbolAddress((void**)&t0,   g_t0);
    cudaGetSymbolAddress((void**)&t1,   g_t1);
    cudaGetSymbolAddress((void**)&tpw1, g_tpw1);
    cudaGetSymbolAddress((void**)&off0, g_off0);
    cudaGetSymbolAddress((void**)&off1, g_off1);
    cudaGetSymbolAddress((void**)&offacc, g_offacc);

    // both wavelet levels in one pass
    k_wt2<<<4096, 256>>>(x, t0, t1);
    // level-1 offsets (16-way split: 256 blocks)
    k_off2<<<dim3(2,2,64), dim3(32,8)>>>(t1, off_w + 2*256*9, offacc, 64, 64);
    k_offfin<<<64, 256>>>(offacc, off_b + 2, (float2*)off1, 64, 64);
    // merged: level-1 snake (512 blocks) + level-0 offset conv (1024 blocks)
    k_mix<<<1536, dim3(32,8)>>>(t1, (const float2*)off1, dw_w + 256*9, pw_w + 256*4,
                                wscale + 256, tpw1, t0, off_w, offacc);
    // level-0 offset finalize
    k_offfin<<<256, 256>>>(offacc, off_b, (float2*)off0, 128, 128);
    // level-0 snake + full reconstruction + base, fused
    k_sdpfin<<<dim3(4,8,64), dim3(32,8)>>>(t0, (const float2*)off0, dw_w, pw_w, wscale,
                                           tpw1, x, base_w, base_b, base_sc, gamma, out);
}